// round 7
// baseline (speedup 1.0000x reference)
#include <cuda_runtime.h>
#include <math.h>

#define BN 16384
#define KC 64
#define DD 128
#define NB 8
#define NBLK_A 256
#define CHE 111
#define NE 148
#define CSTR 92   // cs row stride in words (group q at q*12, 8 floats per group)
#define XSP (DD + 4)

__device__ int   g_assign[BN];
__device__ int   g_bhist[NBLK_A * KC];
__device__ int   g_boff2[64 * KC];     // per 256-sample chunk scatter bases
__device__ int   g_off[KC + 1];
__device__ int   g_sorted[BN];
__device__ float g_meansum[KC * DD];
__device__ float g_mean[KC * DD];
__device__ float g_ms;
__device__ float g_covpart[KC];
__device__ float g_cov[KC * DD * DD];
__device__ int   g_tickA, g_tickD, g_tickF;

// ============ pass A: zero scratch + dist/log_resp/argmin + hist + (ticket) prefix ============
// thread: 2 samples x 8 clusters (octant q = tid&7), 128 dims.
__global__ __launch_bounds__(256) void k_passA(const float* __restrict__ x,
                                               const float* __restrict__ cen,
                                               float* __restrict__ out) {
    __shared__ float cs[DD * CSTR];   // 47104 B, bank-conflict-free float4 groups
    __shared__ float cn2s[KC];
    __shared__ int hist_s[KC];
    __shared__ int isLast;
    int tid = threadIdx.x;

    // ---- fold: zero g_cov / g_meansum slices ----
    {
        float4 z = make_float4(0.f, 0.f, 0.f, 0.f);
        float4* cz = ((float4*)g_cov) + (size_t)blockIdx.x * 1024;
        for (int i = tid; i < 1024; i += 256) cz[i] = z;
        if (tid < 8) ((float4*)g_meansum)[blockIdx.x * 8 + tid] = z;
    }

    if (tid < KC) hist_s[tid] = 0;
    for (int i = tid; i < KC * DD; i += 256) {
        int k = i >> 7, d = i & 127;
        cs[d * CSTR + (k >> 3) * 12 + (k & 7)] = cen[i];
    }
    if (tid < KC) {
        const float* cr = cen + tid * DD;
        float s0 = 0.f, s1 = 0.f, s2 = 0.f, s3 = 0.f;
        for (int d = 0; d < DD; d += 4) {
            s0 += cr[d] * cr[d];
            s1 += cr[d + 1] * cr[d + 1];
            s2 += cr[d + 2] * cr[d + 2];
            s3 += cr[d + 3] * cr[d + 3];
        }
        cn2s[tid] = (s0 + s1) + (s2 + s3);
    }
    __syncthreads();

    int g = blockIdx.x * 256 + tid;
    int q = g & 7;
    int pairI = g >> 3;
    int n0 = pairI * 2, n1 = n0 + 1;

    const float4* x40 = (const float4*)(x + (size_t)n0 * DD);
    const float4* x41 = (const float4*)(x + (size_t)n1 * DD);

    float acc0[8], acc1[8];
#pragma unroll
    for (int kl = 0; kl < 8; ++kl) { acc0[kl] = 0.f; acc1[kl] = 0.f; }
    float xn20 = 0.f, xn21 = 0.f;

#pragma unroll 4
    for (int ch = 0; ch < 16; ++ch) {
        float4 a = x40[ch * 2], b = x40[ch * 2 + 1];
        float4 c4 = x41[ch * 2], d4 = x41[ch * 2 + 1];
        float xa[8] = {a.x, a.y, a.z, a.w, b.x, b.y, b.z, b.w};
        float xb[8] = {c4.x, c4.y, c4.z, c4.w, d4.x, d4.y, d4.z, d4.w};
#pragma unroll
        for (int j = 0; j < 8; ++j) {
            xn20 = fmaf(xa[j], xa[j], xn20);
            xn21 = fmaf(xb[j], xb[j], xn21);
        }
        const float* cp = &cs[(ch * 8) * CSTR + q * 12];
#pragma unroll
        for (int j = 0; j < 8; ++j) {
            float4 ca = *(const float4*)(cp + j * CSTR);
            float4 cb2 = *(const float4*)(cp + j * CSTR + 4);
            acc0[0] = fmaf(xa[j], ca.x, acc0[0]);
            acc0[1] = fmaf(xa[j], ca.y, acc0[1]);
            acc0[2] = fmaf(xa[j], ca.z, acc0[2]);
            acc0[3] = fmaf(xa[j], ca.w, acc0[3]);
            acc0[4] = fmaf(xa[j], cb2.x, acc0[4]);
            acc0[5] = fmaf(xa[j], cb2.y, acc0[5]);
            acc0[6] = fmaf(xa[j], cb2.z, acc0[6]);
            acc0[7] = fmaf(xa[j], cb2.w, acc0[7]);
            acc1[0] = fmaf(xb[j], ca.x, acc1[0]);
            acc1[1] = fmaf(xb[j], ca.y, acc1[1]);
            acc1[2] = fmaf(xb[j], ca.z, acc1[2]);
            acc1[3] = fmaf(xb[j], ca.w, acc1[3]);
            acc1[4] = fmaf(xb[j], cb2.x, acc1[4]);
            acc1[5] = fmaf(xb[j], cb2.y, acc1[5]);
            acc1[6] = fmaf(xb[j], cb2.z, acc1[6]);
            acc1[7] = fmaf(xb[j], cb2.w, acc1[7]);
        }
    }

    float dist0[8], dist1[8];
    float dmin0 = 3.4e38f, dmin1 = 3.4e38f;
    int km0 = 0, km1 = 0;
#pragma unroll
    for (int kl = 0; kl < 8; ++kl) {
        float cn2 = cn2s[q * 8 + kl];
        float dv0 = fmaf(-2.f, acc0[kl], xn20 + cn2);
        float dv1 = fmaf(-2.f, acc1[kl], xn21 + cn2);
        dist0[kl] = dv0; dist1[kl] = dv1;
        if (dv0 < dmin0) { dmin0 = dv0; km0 = q * 8 + kl; }
        if (dv1 < dmin1) { dmin1 = dv1; km1 = q * 8 + kl; }
    }
#pragma unroll
    for (int m = 1; m < 8; m <<= 1) {
        float ov0 = __shfl_xor_sync(0xffffffffu, dmin0, m);
        int   oi0 = __shfl_xor_sync(0xffffffffu, km0, m);
        if (ov0 < dmin0 || (ov0 == dmin0 && oi0 < km0)) { dmin0 = ov0; km0 = oi0; }
        float ov1 = __shfl_xor_sync(0xffffffffu, dmin1, m);
        int   oi1 = __shfl_xor_sync(0xffffffffu, km1, m);
        if (ov1 < dmin1 || (ov1 == dmin1 && oi1 < km1)) { dmin1 = ov1; km1 = oi1; }
    }
    float ls0 = 0.f, ls1 = 0.f;
#pragma unroll
    for (int kl = 0; kl < 8; ++kl) {
        ls0 += __expf(-0.5f * (dist0[kl] - dmin0));
        ls1 += __expf(-0.5f * (dist1[kl] - dmin1));
    }
#pragma unroll
    for (int m = 1; m < 8; m <<= 1) {
        ls0 += __shfl_xor_sync(0xffffffffu, ls0, m);
        ls1 += __shfl_xor_sync(0xffffffffu, ls1, m);
    }
    float lg0 = logf(ls0), lg1 = logf(ls1);
    const float LM = logf(1e-8f);

    float4* o0 = (float4*)(out + (size_t)n0 * KC + q * 8);
    float4* o1 = (float4*)(out + (size_t)n1 * KC + q * 8);
#pragma unroll
    for (int v = 0; v < 2; ++v) {
        float4 r0, r1;
        r0.x = fmaxf(-0.5f * (dist0[4 * v + 0] - dmin0) - lg0, LM);
        r0.y = fmaxf(-0.5f * (dist0[4 * v + 1] - dmin0) - lg0, LM);
        r0.z = fmaxf(-0.5f * (dist0[4 * v + 2] - dmin0) - lg0, LM);
        r0.w = fmaxf(-0.5f * (dist0[4 * v + 3] - dmin0) - lg0, LM);
        r1.x = fmaxf(-0.5f * (dist1[4 * v + 0] - dmin1) - lg1, LM);
        r1.y = fmaxf(-0.5f * (dist1[4 * v + 1] - dmin1) - lg1, LM);
        r1.z = fmaxf(-0.5f * (dist1[4 * v + 2] - dmin1) - lg1, LM);
        r1.w = fmaxf(-0.5f * (dist1[4 * v + 3] - dmin1) - lg1, LM);
        o0[v] = r0; o1[v] = r1;
    }
    if (q == 0) {
        g_assign[n0] = km0;
        g_assign[n1] = km1;
        atomicAdd(&hist_s[km0], 1);
        atomicAdd(&hist_s[km1], 1);
    }
    __syncthreads();
    if (tid < KC) g_bhist[blockIdx.x * KC + tid] = hist_s[tid];

    // ---- fold: pass B via last-block ticket ----
    __threadfence();
    __syncthreads();
    if (tid == 0) {
        int v = atomicAdd(&g_tickA, 1);
        isLast = (v == NBLK_A - 1) ? 1 : 0;
    }
    __syncthreads();
    if (!isLast) return;

    // reuse cs storage as int scratch
    int* ibuf = (int*)cs;
    int* partial = ibuf;           // 4*64
    int* pre = ibuf + 256;         // 65
    int* chunkh = ibuf + 384;      // 64*64

    for (int i = tid; i < 64 * KC; i += 256) {
        int c = i >> 6, k = i & 63;
        int b0 = c * 4;
        chunkh[i] = g_bhist[b0 * KC + k] + g_bhist[(b0 + 1) * KC + k]
                  + g_bhist[(b0 + 2) * KC + k] + g_bhist[(b0 + 3) * KC + k];
    }
    __syncthreads();
    {
        int k = tid & 63, grp = tid >> 6;
        int s = 0;
        for (int c = grp * 16; c < grp * 16 + 16; ++c) s += chunkh[c * KC + k];
        partial[grp * KC + k] = s;
    }
    __syncthreads();
    if (tid == 0) {
        int acc = 0;
        for (int k = 0; k < KC; ++k) {
            pre[k] = acc;
            acc += partial[k] + partial[KC + k] + partial[2 * KC + k] + partial[3 * KC + k];
        }
        pre[KC] = acc;
        g_tickA = 0;
    }
    __syncthreads();
    if (tid <= KC) g_off[tid] = pre[tid];
    {
        int k = tid & 63, cg = tid >> 6;
        int run = pre[k];
        for (int g2 = 0; g2 < cg; ++g2) run += partial[g2 * KC + k];
        for (int c = cg * 16; c < cg * 16 + 16; ++c) {
            g_boff2[c * KC + k] = run;
            run += chunkh[c * KC + k];
        }
    }
}

// ============ pass C: counting-sort scatter, 256 samples/block ============
__global__ __launch_bounds__(256) void k_passC() {
    __shared__ int cnt[KC];
    __shared__ int base[KC];
    int t = threadIdx.x, b = blockIdx.x;
    if (t < KC) { cnt[t] = 0; base[t] = g_boff2[b * KC + t]; }
    __syncthreads();
    int n = b * 256 + t;
    int a = g_assign[n];
    int r = atomicAdd(&cnt[a], 1);
    g_sorted[base[a] + r] = n;
}

// ============ pass D1: balanced segment sums + (ticket) mean normalize + mean_mse ============
__global__ __launch_bounds__(128) void k_passD1(const float* __restrict__ x,
                                                const float* __restrict__ cen) {
    __shared__ int offs[KC + 1];
    __shared__ int isLast;
    __shared__ float red[4];
    int t = threadIdx.x;
    if (t <= KC) offs[t] = g_off[t];
    __syncthreads();

    int p0 = blockIdx.x * 128, p1 = p0 + 128;
    int k = 0;
    while (offs[k + 1] <= p0) k++;
    int segEnd = offs[k + 1];
    float acc = 0.f;
    for (int p = p0; p < p1; ++p) {
        while (p >= segEnd) {
            if (acc != 0.f) atomicAdd(&g_meansum[k * DD + t], acc);
            acc = 0.f;
            k++;
            segEnd = offs[k + 1];
        }
        acc += x[(size_t)g_sorted[p] * DD + t];
    }
    if (acc != 0.f) atomicAdd(&g_meansum[k * DD + t], acc);

    __threadfence();
    __syncthreads();
    if (t == 0) {
        int v = atomicAdd(&g_tickD, 1);
        isLast = (v == gridDim.x - 1) ? 1 : 0;
    }
    __syncthreads();
    if (!isLast) return;

    float msAcc = 0.f;
    for (int kk = 0; kk < KC; ++kk) {
        float w = (float)(offs[kk + 1] - offs[kk]);
        float m = g_meansum[kk * DD + t] / (w + 1e-7f);
        g_mean[kk * DD + t] = m;
        float d = m - cen[kk * DD + t];
        msAcc = fmaf(w * d, d, msAcc);
    }
#pragma unroll
    for (int m = 16; m > 0; m >>= 1) msAcc += __shfl_xor_sync(0xffffffffu, msAcc, m);
    if ((t & 31) == 0) red[t >> 5] = msAcc;
    __syncthreads();
    if (t == 0) {
        g_ms = red[0] + red[1] + red[2] + red[3];
        g_tickD = 0;
    }
}

// ============ pass E: symmetric covariance SYRK (upper triangle only) ============
__global__ __launch_bounds__(256) void k_passE(const float* __restrict__ x) {
    __shared__ float xs[NB][XSP];
    __shared__ float mrow[DD];
    __shared__ int offs[KC + 1];
    int tid = threadIdx.x;
    if (tid <= KC) offs[tid] = g_off[tid];

    // roles: warp0 lanes 0-15 -> 16 diagonal tiles, full batch.
    // remaining 240 lanes -> 120 upper tiles x 2 batch-halves.
    int w = tid >> 5, l = tid & 31;
    int ti, tj, sBeg, sEnd;
    if (w == 0 && l < 16) {
        ti = l; tj = l; sBeg = 0; sEnd = NB;
    } else {
        int slot = (w == 0) ? (l - 16) : (16 + (w - 1) * 32 + l);   // 0..239
        int h = (slot >= 120) ? 1 : 0;
        int u = slot - h * 120;
        int a = 0, cnt = 15, rem = u;
        while (rem >= cnt) { rem -= cnt; a++; cnt--; }
        ti = a; tj = a + 1 + rem;
        sBeg = h * (NB / 2); sEnd = sBeg + NB / 2;
    }
    int ri = ti * 8, cj = tj * 8;
    __syncthreads();

    int p0 = blockIdx.x * CHE;
    int p1 = min(p0 + CHE, BN);

    int k = 0;
    while (k < KC && offs[k + 1] <= p0) k++;
    for (; k < KC && offs[k] < p1; ++k) {
        int s0 = max(offs[k], p0), s1 = min(offs[k + 1], p1);
        if (s1 <= s0) continue;

        float acc[8][8];
#pragma unroll
        for (int i = 0; i < 8; ++i)
#pragma unroll
            for (int j = 0; j < 8; ++j) acc[i][j] = 0.f;

        __syncthreads();
        if (tid < DD) mrow[tid] = g_mean[k * DD + tid];

        for (int base = s0; base < s1; base += NB) {
            __syncthreads();
#pragma unroll
            for (int u = tid; u < NB * DD; u += 256) {
                int s = u >> 7, d = u & 127;
                int pos = base + s;
                float v = 0.f;
                if (pos < s1) v = x[(size_t)g_sorted[pos] * DD + d] - mrow[d];
                xs[s][d] = v;
            }
            __syncthreads();
            for (int s = sBeg; s < sEnd; ++s) {
                float rv[8], cv[8];
#pragma unroll
                for (int i = 0; i < 8; ++i) rv[i] = xs[s][ri + i];
#pragma unroll
                for (int j = 0; j < 8; ++j) cv[j] = xs[s][cj + j];
#pragma unroll
                for (int i = 0; i < 8; ++i)
#pragma unroll
                    for (int j = 0; j < 8; ++j) acc[i][j] = fmaf(rv[i], cv[j], acc[i][j]);
            }
        }
        float* cb = g_cov + (size_t)k * DD * DD;
#pragma unroll
        for (int i = 0; i < 8; ++i)
#pragma unroll
            for (int j = 0; j < 8; ++j)
                atomicAdd(&cb[(ri + i) * DD + cj + j], acc[i][j]);
    }
}

// ============ pass F1: diag/off terms (upper-tri aware) + (ticket) final scalars ============
__global__ __launch_bounds__(256) void k_passF1(float* __restrict__ out_scalars) {
    __shared__ float rd[256], ro[256];
    __shared__ int isLast;
    int k = blockIdx.x, tid = threadIdx.x;
    float w = (float)(g_off[k + 1] - g_off[k]);
    float inv = 1.f / (w + 1e-7f);
    const float* cb = g_cov + (size_t)k * DD * DD;
    float ds = 0.f, os = 0.f;
    for (int i = tid; i < DD * DD; i += 256) {
        int d = i >> 7, e = i & 127;
        if (e < d) continue;
        float cv = cb[i] * inv;
        if (d == e) { float t2 = cv - 1.f; ds += t2 * t2; }
        else os += cv * cv;
    }
    rd[tid] = ds; ro[tid] = os;
    __syncthreads();
    for (int s = 128; s > 0; s >>= 1) {
        if (tid < s) { rd[tid] += rd[tid + s]; ro[tid] += ro[tid + s]; }
        __syncthreads();
    }
    if (tid == 0) {
        float bd = (float)BN * (float)DD;
        g_covpart[k] = w * rd[0] / bd + 2.f * w * ro[0] / (bd * (float)(DD - 1));
    }
    __threadfence();
    __syncthreads();
    if (tid == 0) {
        int v = atomicAdd(&g_tickF, 1);
        isLast = (v == gridDim.x - 1) ? 1 : 0;
    }
    __syncthreads();
    if (!isLast) return;

    float cs2 = (tid < KC) ? g_covpart[tid] : 0.f;
#pragma unroll
    for (int m = 16; m > 0; m >>= 1) cs2 += __shfl_xor_sync(0xffffffffu, cs2, m);
    if ((tid & 31) == 0) rd[tid >> 5] = cs2;
    __syncthreads();
    if (tid == 0) {
        out_scalars[0] = g_ms / ((float)BN * (float)DD);
        out_scalars[1] = rd[0] + rd[1];
        g_tickF = 0;
    }
}

extern "C" void kernel_launch(void* const* d_in, const int* in_sizes, int n_in,
                              void* d_out, int out_size) {
    const float* x = (const float*)d_in[0];
    const float* c = (const float*)d_in[1];
    float* out = (float*)d_out;

    k_passA<<<NBLK_A, 256>>>(x, c, out);
    k_passC<<<64, 256>>>();
    k_passD1<<<BN / 128, 128>>>(x, c);
    k_passE<<<NE, 256>>>(x);
    k_passF1<<<KC, 256>>>(out + (out_size - 2));
}

// round 9
// speedup vs baseline: 1.0791x; 1.0791x over previous
#include <cuda_runtime.h>
#include <cstdint>
#include <math.h>

#define BN 16384
#define KC 64
#define DD 128
#define NBLK_A 256
#define CSTR 92   // cs row stride in words (group q at q*12, 8 floats per group)

#define NBE 8          // samples per passE batch
#define STG 4          // cp.async pipeline stages
#define NBLK_E 296
#define CHE2 56

__device__ int   g_assign[BN];
__device__ int   g_bhist[NBLK_A * KC];
__device__ int   g_boff2[64 * KC];
__device__ int   g_off[KC + 1];
__device__ int   g_sorted[BN];
__device__ float g_meansum[KC * DD];
__device__ float g_ms;
__device__ float g_covpart[KC];
__device__ float g_cov[KC * DD * DD];
__device__ int   g_tickA, g_tickD, g_tickF;

#define CP_ASYNC16(dst, src) \
    asm volatile("cp.async.cg.shared.global [%0], [%1], 16;" :: "r"(dst), "l"(src))
#define CP_COMMIT() asm volatile("cp.async.commit_group;")
#define CP_WAIT3()  asm volatile("cp.async.wait_group 3;")

// ============ pass A: zero scratch + dist/log_resp/argmin + hist + (ticket) prefix ============
__global__ __launch_bounds__(256) void k_passA(const float* __restrict__ x,
                                               const float* __restrict__ cen,
                                               float* __restrict__ out) {
    __shared__ float cs[DD * CSTR];
    __shared__ float cn2s[KC];
    __shared__ int hist_s[KC];
    __shared__ int isLast;
    int tid = threadIdx.x;

    {   // zero g_cov / g_meansum slices
        float4 z = make_float4(0.f, 0.f, 0.f, 0.f);
        float4* cz = ((float4*)g_cov) + (size_t)blockIdx.x * 1024;
        for (int i = tid; i < 1024; i += 256) cz[i] = z;
        if (tid < 8) ((float4*)g_meansum)[blockIdx.x * 8 + tid] = z;
    }

    if (tid < KC) hist_s[tid] = 0;
    for (int i = tid; i < KC * DD; i += 256) {
        int k = i >> 7, d = i & 127;
        cs[d * CSTR + (k >> 3) * 12 + (k & 7)] = cen[i];
    }
    if (tid < KC) {
        const float* cr = cen + tid * DD;
        float s0 = 0.f, s1 = 0.f, s2 = 0.f, s3 = 0.f;
        for (int d = 0; d < DD; d += 4) {
            s0 += cr[d] * cr[d];
            s1 += cr[d + 1] * cr[d + 1];
            s2 += cr[d + 2] * cr[d + 2];
            s3 += cr[d + 3] * cr[d + 3];
        }
        cn2s[tid] = (s0 + s1) + (s2 + s3);
    }
    __syncthreads();

    int g = blockIdx.x * 256 + tid;
    int q = g & 7;
    int pairI = g >> 3;
    int n0 = pairI * 2, n1 = n0 + 1;

    const float4* x40 = (const float4*)(x + (size_t)n0 * DD);
    const float4* x41 = (const float4*)(x + (size_t)n1 * DD);

    float acc0[8], acc1[8];
#pragma unroll
    for (int kl = 0; kl < 8; ++kl) { acc0[kl] = 0.f; acc1[kl] = 0.f; }
    float xn20 = 0.f, xn21 = 0.f;

#pragma unroll 4
    for (int ch = 0; ch < 16; ++ch) {
        float4 a = x40[ch * 2], b = x40[ch * 2 + 1];
        float4 c4 = x41[ch * 2], d4 = x41[ch * 2 + 1];
        float xa[8] = {a.x, a.y, a.z, a.w, b.x, b.y, b.z, b.w};
        float xb[8] = {c4.x, c4.y, c4.z, c4.w, d4.x, d4.y, d4.z, d4.w};
#pragma unroll
        for (int j = 0; j < 8; ++j) {
            xn20 = fmaf(xa[j], xa[j], xn20);
            xn21 = fmaf(xb[j], xb[j], xn21);
        }
        const float* cp = &cs[(ch * 8) * CSTR + q * 12];
#pragma unroll
        for (int j = 0; j < 8; ++j) {
            float4 ca = *(const float4*)(cp + j * CSTR);
            float4 cb2 = *(const float4*)(cp + j * CSTR + 4);
            acc0[0] = fmaf(xa[j], ca.x, acc0[0]);
            acc0[1] = fmaf(xa[j], ca.y, acc0[1]);
            acc0[2] = fmaf(xa[j], ca.z, acc0[2]);
            acc0[3] = fmaf(xa[j], ca.w, acc0[3]);
            acc0[4] = fmaf(xa[j], cb2.x, acc0[4]);
            acc0[5] = fmaf(xa[j], cb2.y, acc0[5]);
            acc0[6] = fmaf(xa[j], cb2.z, acc0[6]);
            acc0[7] = fmaf(xa[j], cb2.w, acc0[7]);
            acc1[0] = fmaf(xb[j], ca.x, acc1[0]);
            acc1[1] = fmaf(xb[j], ca.y, acc1[1]);
            acc1[2] = fmaf(xb[j], ca.z, acc1[2]);
            acc1[3] = fmaf(xb[j], ca.w, acc1[3]);
            acc1[4] = fmaf(xb[j], cb2.x, acc1[4]);
            acc1[5] = fmaf(xb[j], cb2.y, acc1[5]);
            acc1[6] = fmaf(xb[j], cb2.z, acc1[6]);
            acc1[7] = fmaf(xb[j], cb2.w, acc1[7]);
        }
    }

    float dist0[8], dist1[8];
    float dmin0 = 3.4e38f, dmin1 = 3.4e38f;
    int km0 = 0, km1 = 0;
#pragma unroll
    for (int kl = 0; kl < 8; ++kl) {
        float cn2 = cn2s[q * 8 + kl];
        float dv0 = fmaf(-2.f, acc0[kl], xn20 + cn2);
        float dv1 = fmaf(-2.f, acc1[kl], xn21 + cn2);
        dist0[kl] = dv0; dist1[kl] = dv1;
        if (dv0 < dmin0) { dmin0 = dv0; km0 = q * 8 + kl; }
        if (dv1 < dmin1) { dmin1 = dv1; km1 = q * 8 + kl; }
    }
#pragma unroll
    for (int m = 1; m < 8; m <<= 1) {
        float ov0 = __shfl_xor_sync(0xffffffffu, dmin0, m);
        int   oi0 = __shfl_xor_sync(0xffffffffu, km0, m);
        if (ov0 < dmin0 || (ov0 == dmin0 && oi0 < km0)) { dmin0 = ov0; km0 = oi0; }
        float ov1 = __shfl_xor_sync(0xffffffffu, dmin1, m);
        int   oi1 = __shfl_xor_sync(0xffffffffu, km1, m);
        if (ov1 < dmin1 || (ov1 == dmin1 && oi1 < km1)) { dmin1 = ov1; km1 = oi1; }
    }
    float ls0 = 0.f, ls1 = 0.f;
#pragma unroll
    for (int kl = 0; kl < 8; ++kl) {
        ls0 += __expf(-0.5f * (dist0[kl] - dmin0));
        ls1 += __expf(-0.5f * (dist1[kl] - dmin1));
    }
#pragma unroll
    for (int m = 1; m < 8; m <<= 1) {
        ls0 += __shfl_xor_sync(0xffffffffu, ls0, m);
        ls1 += __shfl_xor_sync(0xffffffffu, ls1, m);
    }
    float lg0 = logf(ls0), lg1 = logf(ls1);
    const float LM = logf(1e-8f);

    float4* o0 = (float4*)(out + (size_t)n0 * KC + q * 8);
    float4* o1 = (float4*)(out + (size_t)n1 * KC + q * 8);
#pragma unroll
    for (int v = 0; v < 2; ++v) {
        float4 r0, r1;
        r0.x = fmaxf(-0.5f * (dist0[4 * v + 0] - dmin0) - lg0, LM);
        r0.y = fmaxf(-0.5f * (dist0[4 * v + 1] - dmin0) - lg0, LM);
        r0.z = fmaxf(-0.5f * (dist0[4 * v + 2] - dmin0) - lg0, LM);
        r0.w = fmaxf(-0.5f * (dist0[4 * v + 3] - dmin0) - lg0, LM);
        r1.x = fmaxf(-0.5f * (dist1[4 * v + 0] - dmin1) - lg1, LM);
        r1.y = fmaxf(-0.5f * (dist1[4 * v + 1] - dmin1) - lg1, LM);
        r1.z = fmaxf(-0.5f * (dist1[4 * v + 2] - dmin1) - lg1, LM);
        r1.w = fmaxf(-0.5f * (dist1[4 * v + 3] - dmin1) - lg1, LM);
        o0[v] = r0; o1[v] = r1;
    }
    if (q == 0) {
        g_assign[n0] = km0;
        g_assign[n1] = km1;
        atomicAdd(&hist_s[km0], 1);
        atomicAdd(&hist_s[km1], 1);
    }
    __syncthreads();
    if (tid < KC) g_bhist[blockIdx.x * KC + tid] = hist_s[tid];

    __threadfence();
    __syncthreads();
    if (tid == 0) {
        int v = atomicAdd(&g_tickA, 1);
        isLast = (v == NBLK_A - 1) ? 1 : 0;
    }
    __syncthreads();
    if (!isLast) return;

    int* ibuf = (int*)cs;
    int* partial = ibuf;           // 4*64
    int* pre = ibuf + 256;         // 65
    int* chunkh = ibuf + 384;      // 64*64

    for (int i = tid; i < 64 * KC; i += 256) {
        int c = i >> 6, k = i & 63;
        int b0 = c * 4;
        chunkh[i] = g_bhist[b0 * KC + k] + g_bhist[(b0 + 1) * KC + k]
                  + g_bhist[(b0 + 2) * KC + k] + g_bhist[(b0 + 3) * KC + k];
    }
    __syncthreads();
    {
        int k = tid & 63, grp = tid >> 6;
        int s = 0;
        for (int c = grp * 16; c < grp * 16 + 16; ++c) s += chunkh[c * KC + k];
        partial[grp * KC + k] = s;
    }
    __syncthreads();
    if (tid == 0) {
        int acc = 0;
        for (int k = 0; k < KC; ++k) {
            pre[k] = acc;
            acc += partial[k] + partial[KC + k] + partial[2 * KC + k] + partial[3 * KC + k];
        }
        pre[KC] = acc;
        g_tickA = 0;
    }
    __syncthreads();
    if (tid <= KC) g_off[tid] = pre[tid];
    {
        int k = tid & 63, cg = tid >> 6;
        int run = pre[k];
        for (int g2 = 0; g2 < cg; ++g2) run += partial[g2 * KC + k];
        for (int c = cg * 16; c < cg * 16 + 16; ++c) {
            g_boff2[c * KC + k] = run;
            run += chunkh[c * KC + k];
        }
    }
}

// ============ pass C: counting-sort scatter ============
__global__ __launch_bounds__(256) void k_passC() {
    __shared__ int cnt[KC];
    __shared__ int base[KC];
    int t = threadIdx.x, b = blockIdx.x;
    if (t < KC) { cnt[t] = 0; base[t] = g_boff2[b * KC + t]; }
    __syncthreads();
    int n = b * 256 + t;
    int a = g_assign[n];
    int r = atomicAdd(&cnt[a], 1);
    g_sorted[base[a] + r] = n;
}

// ============ pass D1: balanced segment sums + (ticket) mean_mse ============
__global__ __launch_bounds__(128) void k_passD1(const float* __restrict__ x,
                                                const float* __restrict__ cen) {
    __shared__ int offs[KC + 1];
    __shared__ int isLast;
    __shared__ float red[4];
    int t = threadIdx.x;
    if (t <= KC) offs[t] = g_off[t];
    __syncthreads();

    int p0 = blockIdx.x * 64, p1 = p0 + 64;
    int k = 0;
    while (offs[k + 1] <= p0) k++;
    int segEnd = offs[k + 1];
    float acc = 0.f;
    for (int p = p0; p < p1; ++p) {
        while (p >= segEnd) {
            if (acc != 0.f) atomicAdd(&g_meansum[k * DD + t], acc);
            acc = 0.f;
            k++;
            segEnd = offs[k + 1];
        }
        acc += x[(size_t)g_sorted[p] * DD + t];
    }
    if (acc != 0.f) atomicAdd(&g_meansum[k * DD + t], acc);

    __threadfence();
    __syncthreads();
    if (t == 0) {
        int v = atomicAdd(&g_tickD, 1);
        isLast = (v == gridDim.x - 1) ? 1 : 0;
    }
    __syncthreads();
    if (!isLast) return;

    float msAcc = 0.f;
    for (int kk = 0; kk < KC; ++kk) {
        float w = (float)(offs[kk + 1] - offs[kk]);
        float m = g_meansum[kk * DD + t] / (w + 1e-7f);
        float d = m - cen[kk * DD + t];
        msAcc = fmaf(w * d, d, msAcc);
    }
#pragma unroll
    for (int m = 16; m > 0; m >>= 1) msAcc += __shfl_xor_sync(0xffffffffu, msAcc, m);
    if ((t & 31) == 0) red[t >> 5] = msAcc;
    __syncthreads();
    if (t == 0) {
        g_ms = red[0] + red[1] + red[2] + red[3];
        g_tickD = 0;
    }
}

// ============ pass E: raw-moment SYRK, cp.async 4-stage pipeline, upper triangle ============
__global__ __launch_bounds__(256) void k_passE(const float* __restrict__ x) {
    __shared__ float xs[STG][NBE][DD];    // 16 KB
    __shared__ int offs[KC + 1];
    __shared__ int sidx[CHE2];
    int tid = threadIdx.x;

    int p0 = blockIdx.x * CHE2;
    if (p0 >= BN) return;                 // uniform per-block
    int p1 = min(p0 + CHE2, BN);

    if (tid <= KC) offs[tid] = g_off[tid];
    for (int i = tid; i < p1 - p0; i += 256) sidx[i] = g_sorted[p0 + i];

    // roles: warp0 lanes 0-15 -> diag tiles (full batch); 240 lanes -> 120 upper tiles x 2 halves
    int w = tid >> 5, l = tid & 31;
    int ti, tj, sBeg, sEnd;
    if (w == 0 && l < 16) {
        ti = l; tj = l; sBeg = 0; sEnd = NBE;
    } else {
        int slot = (w == 0) ? (l - 16) : (16 + (w - 1) * 32 + l);
        int h = (slot >= 120) ? 1 : 0;
        int u = slot - h * 120;
        int a = 0, cnt = 15, rem = u;
        while (rem >= cnt) { rem -= cnt; a++; cnt--; }
        ti = a; tj = a + 1 + rem;
        sBeg = h * (NBE / 2); sEnd = sBeg + NBE / 2;
    }
    int ri = ti * 8, cj = tj * 8;

    int myS = tid >> 5;          // sample slot 0..7
    int myQ = tid & 31;          // float4 index 0..31
    __syncthreads();

    int k = 0;
    while (k < KC && offs[k + 1] <= p0) k++;
    for (; k < KC && offs[k] < p1; ++k) {
        int s0 = max(offs[k], p0), s1 = min(offs[k + 1], p1);
        if (s1 <= s0) continue;

        float acc[8][8];
#pragma unroll
        for (int i = 0; i < 8; ++i)
#pragma unroll
            for (int j = 0; j < 8; ++j) acc[i][j] = 0.f;

        int nb = (s1 - s0 + NBE - 1) / NBE;

        // prologue: issue batches 0..STG-1 (guarded), always commit
#pragma unroll
        for (int pb = 0; pb < STG; ++pb) {
            int base = s0 + pb * NBE;
            if (base < s1) {
                int pos = base + myS;
                float* dgen = &xs[pb][myS][myQ * 4];
                if (pos < s1) {
                    const float* src = x + (size_t)sidx[pos - p0] * DD + myQ * 4;
                    unsigned int dst = (unsigned int)__cvta_generic_to_shared(dgen);
                    CP_ASYNC16(dst, src);
                } else {
                    *(float4*)dgen = make_float4(0.f, 0.f, 0.f, 0.f);
                }
            }
            CP_COMMIT();
        }

        for (int bi = 0; bi < nb; ++bi) {
            CP_WAIT3();
            __syncthreads();
            int st = bi & (STG - 1);
            for (int s = sBeg; s < sEnd; ++s) {
                float rv[8], cv[8];
#pragma unroll
                for (int i = 0; i < 8; ++i) rv[i] = xs[st][s][ri + i];
#pragma unroll
                for (int j = 0; j < 8; ++j) cv[j] = xs[st][s][cj + j];
#pragma unroll
                for (int i = 0; i < 8; ++i)
#pragma unroll
                    for (int j = 0; j < 8; ++j) acc[i][j] = fmaf(rv[i], cv[j], acc[i][j]);
            }
            __syncthreads();
            // issue batch bi+STG into the just-freed stage
            {
                int base = s0 + (bi + STG) * NBE;
                if (base < s1) {
                    int pos = base + myS;
                    float* dgen = &xs[st][myS][myQ * 4];
                    if (pos < s1) {
                        const float* src = x + (size_t)sidx[pos - p0] * DD + myQ * 4;
                        unsigned int dst = (unsigned int)__cvta_generic_to_shared(dgen);
                        CP_ASYNC16(dst, src);
                    } else {
                        *(float4*)dgen = make_float4(0.f, 0.f, 0.f, 0.f);
                    }
                }
                CP_COMMIT();
            }
        }

        float* cb = g_cov + (size_t)k * DD * DD;
#pragma unroll
        for (int i = 0; i < 8; ++i)
#pragma unroll
            for (int j = 0; j < 8; ++j)
                atomicAdd(&cb[(ri + i) * DD + cj + j], acc[i][j]);
    }
}

// ============ pass F1: covar from raw moments + (ticket) final scalars ============
__global__ __launch_bounds__(256) void k_passF1(float* __restrict__ out_scalars) {
    __shared__ float rd[256], ro[256];
    __shared__ float Trow[DD];
    __shared__ int isLast;
    int k = blockIdx.x, tid = threadIdx.x;
    float w = (float)(g_off[k + 1] - g_off[k]);
    float inv = 1.f / (w + 1e-7f);
    float c2 = inv * (2.f - w * inv);     // exact epsilon-aware cross-term factor
    if (tid < DD) Trow[tid] = g_meansum[k * DD + tid];
    __syncthreads();

    const float* cb = g_cov + (size_t)k * DD * DD;
    float ds = 0.f, os = 0.f;
    for (int i = tid; i < DD * DD; i += 256) {
        int d = i >> 7, e = i & 127;
        if (e < d) continue;
        float S = cb[i];
        float cv = (S - c2 * Trow[d] * Trow[e]) * inv;
        if (d == e) { float t2 = cv - 1.f; ds += t2 * t2; }
        else os += cv * cv;
    }
    rd[tid] = ds; ro[tid] = os;
    __syncthreads();
    for (int s = 128; s > 0; s >>= 1) {
        if (tid < s) { rd[tid] += rd[tid + s]; ro[tid] += ro[tid + s]; }
        __syncthreads();
    }
    if (tid == 0) {
        float bd = (float)BN * (float)DD;
        g_covpart[k] = w * rd[0] / bd + 2.f * w * ro[0] / (bd * (float)(DD - 1));
    }
    __threadfence();
    __syncthreads();
    if (tid == 0) {
        int v = atomicAdd(&g_tickF, 1);
        isLast = (v == gridDim.x - 1) ? 1 : 0;
    }
    __syncthreads();
    if (!isLast) return;

    float cs2 = (tid < KC) ? g_covpart[tid] : 0.f;
#pragma unroll
    for (int m = 16; m > 0; m >>= 1) cs2 += __shfl_xor_sync(0xffffffffu, cs2, m);
    if ((tid & 31) == 0) rd[tid >> 5] = cs2;
    __syncthreads();
    if (tid == 0) {
        out_scalars[0] = g_ms / ((float)BN * (float)DD);
        out_scalars[1] = rd[0] + rd[1];
        g_tickF = 0;
    }
}

extern "C" void kernel_launch(void* const* d_in, const int* in_sizes, int n_in,
                              void* d_out, int out_size) {
    const float* x = (const float*)d_in[0];
    const float* c = (const float*)d_in[1];
    float* out = (float*)d_out;

    k_passA<<<NBLK_A, 256>>>(x, c, out);
    k_passC<<<64, 256>>>();
    k_passE<<<NBLK_E, 256>>>(x);
    k_passD1<<<BN / 64, 128>>>(x, c);
    k_passF1<<<KC, 256>>>(out + (out_size - 2));
}

// round 10
// speedup vs baseline: 1.4674x; 1.3599x over previous
#include <cuda_runtime.h>
#include <cstdint>
#include <math.h>

#define BN 16384
#define KC 64
#define DD 128
#define NBLK_A 256
#define CSTR 92   // cs row stride in words (group q at q*12, 8 floats per group)

#define NBE 8          // samples per passE batch
#define STG 4          // cp.async pipeline stages
#define NBLK_E 296
#define CHE2 56

__device__ int   g_assign[BN];
__device__ int   g_bhist[NBLK_A * KC];
__device__ int   g_boff2[64 * KC];
__device__ int   g_off[KC + 1];
__device__ int   g_sorted[BN];
__device__ float g_meansum[KC * DD];
__device__ float g_covpart[KC];
__device__ float g_meanpart[KC];
__device__ float g_cov[KC * DD * DD];
__device__ int   g_tickA, g_tickF;

#define CP_ASYNC16(dst, src) \
    asm volatile("cp.async.cg.shared.global [%0], [%1], 16;" :: "r"(dst), "l"(src))
#define CP_COMMIT() asm volatile("cp.async.commit_group;")
#define CP_WAIT3()  asm volatile("cp.async.wait_group 3;")

// ============ pass A: zero scratch + dist/log_resp/argmin + hist + (ticket) prefix ============
__global__ __launch_bounds__(256) void k_passA(const float* __restrict__ x,
                                               const float* __restrict__ cen,
                                               float* __restrict__ out) {
    __shared__ float cs[DD * CSTR];
    __shared__ float cn2s[KC];
    __shared__ int hist_s[KC];
    __shared__ int isLast;
    int tid = threadIdx.x;

    {   // zero g_cov / g_meansum slices
        float4 z = make_float4(0.f, 0.f, 0.f, 0.f);
        float4* cz = ((float4*)g_cov) + (size_t)blockIdx.x * 1024;
        for (int i = tid; i < 1024; i += 256) cz[i] = z;
        if (tid < 8) ((float4*)g_meansum)[blockIdx.x * 8 + tid] = z;
    }

    if (tid < KC) hist_s[tid] = 0;
    for (int i = tid; i < KC * DD; i += 256) {
        int k = i >> 7, d = i & 127;
        cs[d * CSTR + (k >> 3) * 12 + (k & 7)] = cen[i];
    }
    if (tid < KC) {
        const float* cr = cen + tid * DD;
        float s0 = 0.f, s1 = 0.f, s2 = 0.f, s3 = 0.f;
        for (int d = 0; d < DD; d += 4) {
            s0 += cr[d] * cr[d];
            s1 += cr[d + 1] * cr[d + 1];
            s2 += cr[d + 2] * cr[d + 2];
            s3 += cr[d + 3] * cr[d + 3];
        }
        cn2s[tid] = (s0 + s1) + (s2 + s3);
    }
    __syncthreads();

    int g = blockIdx.x * 256 + tid;
    int q = g & 7;
    int pairI = g >> 3;
    int n0 = pairI * 2, n1 = n0 + 1;

    const float4* x40 = (const float4*)(x + (size_t)n0 * DD);
    const float4* x41 = (const float4*)(x + (size_t)n1 * DD);

    float acc0[8], acc1[8];
#pragma unroll
    for (int kl = 0; kl < 8; ++kl) { acc0[kl] = 0.f; acc1[kl] = 0.f; }
    float xn20 = 0.f, xn21 = 0.f;

#pragma unroll 4
    for (int ch = 0; ch < 16; ++ch) {
        float4 a = x40[ch * 2], b = x40[ch * 2 + 1];
        float4 c4 = x41[ch * 2], d4 = x41[ch * 2 + 1];
        float xa[8] = {a.x, a.y, a.z, a.w, b.x, b.y, b.z, b.w};
        float xb[8] = {c4.x, c4.y, c4.z, c4.w, d4.x, d4.y, d4.z, d4.w};
#pragma unroll
        for (int j = 0; j < 8; ++j) {
            xn20 = fmaf(xa[j], xa[j], xn20);
            xn21 = fmaf(xb[j], xb[j], xn21);
        }
        const float* cp = &cs[(ch * 8) * CSTR + q * 12];
#pragma unroll
        for (int j = 0; j < 8; ++j) {
            float4 ca = *(const float4*)(cp + j * CSTR);
            float4 cb2 = *(const float4*)(cp + j * CSTR + 4);
            acc0[0] = fmaf(xa[j], ca.x, acc0[0]);
            acc0[1] = fmaf(xa[j], ca.y, acc0[1]);
            acc0[2] = fmaf(xa[j], ca.z, acc0[2]);
            acc0[3] = fmaf(xa[j], ca.w, acc0[3]);
            acc0[4] = fmaf(xa[j], cb2.x, acc0[4]);
            acc0[5] = fmaf(xa[j], cb2.y, acc0[5]);
            acc0[6] = fmaf(xa[j], cb2.z, acc0[6]);
            acc0[7] = fmaf(xa[j], cb2.w, acc0[7]);
            acc1[0] = fmaf(xb[j], ca.x, acc1[0]);
            acc1[1] = fmaf(xb[j], ca.y, acc1[1]);
            acc1[2] = fmaf(xb[j], ca.z, acc1[2]);
            acc1[3] = fmaf(xb[j], ca.w, acc1[3]);
            acc1[4] = fmaf(xb[j], cb2.x, acc1[4]);
            acc1[5] = fmaf(xb[j], cb2.y, acc1[5]);
            acc1[6] = fmaf(xb[j], cb2.z, acc1[6]);
            acc1[7] = fmaf(xb[j], cb2.w, acc1[7]);
        }
    }

    float dist0[8], dist1[8];
    float dmin0 = 3.4e38f, dmin1 = 3.4e38f;
    int km0 = 0, km1 = 0;
#pragma unroll
    for (int kl = 0; kl < 8; ++kl) {
        float cn2 = cn2s[q * 8 + kl];
        float dv0 = fmaf(-2.f, acc0[kl], xn20 + cn2);
        float dv1 = fmaf(-2.f, acc1[kl], xn21 + cn2);
        dist0[kl] = dv0; dist1[kl] = dv1;
        if (dv0 < dmin0) { dmin0 = dv0; km0 = q * 8 + kl; }
        if (dv1 < dmin1) { dmin1 = dv1; km1 = q * 8 + kl; }
    }
#pragma unroll
    for (int m = 1; m < 8; m <<= 1) {
        float ov0 = __shfl_xor_sync(0xffffffffu, dmin0, m);
        int   oi0 = __shfl_xor_sync(0xffffffffu, km0, m);
        if (ov0 < dmin0 || (ov0 == dmin0 && oi0 < km0)) { dmin0 = ov0; km0 = oi0; }
        float ov1 = __shfl_xor_sync(0xffffffffu, dmin1, m);
        int   oi1 = __shfl_xor_sync(0xffffffffu, km1, m);
        if (ov1 < dmin1 || (ov1 == dmin1 && oi1 < km1)) { dmin1 = ov1; km1 = oi1; }
    }
    float ls0 = 0.f, ls1 = 0.f;
#pragma unroll
    for (int kl = 0; kl < 8; ++kl) {
        ls0 += __expf(-0.5f * (dist0[kl] - dmin0));
        ls1 += __expf(-0.5f * (dist1[kl] - dmin1));
    }
#pragma unroll
    for (int m = 1; m < 8; m <<= 1) {
        ls0 += __shfl_xor_sync(0xffffffffu, ls0, m);
        ls1 += __shfl_xor_sync(0xffffffffu, ls1, m);
    }
    float lg0 = logf(ls0), lg1 = logf(ls1);
    const float LM = logf(1e-8f);

    float4* o0 = (float4*)(out + (size_t)n0 * KC + q * 8);
    float4* o1 = (float4*)(out + (size_t)n1 * KC + q * 8);
#pragma unroll
    for (int v = 0; v < 2; ++v) {
        float4 r0, r1;
        r0.x = fmaxf(-0.5f * (dist0[4 * v + 0] - dmin0) - lg0, LM);
        r0.y = fmaxf(-0.5f * (dist0[4 * v + 1] - dmin0) - lg0, LM);
        r0.z = fmaxf(-0.5f * (dist0[4 * v + 2] - dmin0) - lg0, LM);
        r0.w = fmaxf(-0.5f * (dist0[4 * v + 3] - dmin0) - lg0, LM);
        r1.x = fmaxf(-0.5f * (dist1[4 * v + 0] - dmin1) - lg1, LM);
        r1.y = fmaxf(-0.5f * (dist1[4 * v + 1] - dmin1) - lg1, LM);
        r1.z = fmaxf(-0.5f * (dist1[4 * v + 2] - dmin1) - lg1, LM);
        r1.w = fmaxf(-0.5f * (dist1[4 * v + 3] - dmin1) - lg1, LM);
        o0[v] = r0; o1[v] = r1;
    }
    if (q == 0) {
        g_assign[n0] = km0;
        g_assign[n1] = km1;
        atomicAdd(&hist_s[km0], 1);
        atomicAdd(&hist_s[km1], 1);
    }
    __syncthreads();
    if (tid < KC) g_bhist[blockIdx.x * KC + tid] = hist_s[tid];

    __threadfence();
    __syncthreads();
    if (tid == 0) {
        int v = atomicAdd(&g_tickA, 1);
        isLast = (v == NBLK_A - 1) ? 1 : 0;
    }
    __syncthreads();
    if (!isLast) return;

    int* ibuf = (int*)cs;
    int* partial = ibuf;           // 4*64
    int* pre = ibuf + 256;         // 65
    int* chunkh = ibuf + 384;      // 64*64

    for (int i = tid; i < 64 * KC; i += 256) {
        int c = i >> 6, k = i & 63;
        int b0 = c * 4;
        chunkh[i] = g_bhist[b0 * KC + k] + g_bhist[(b0 + 1) * KC + k]
                  + g_bhist[(b0 + 2) * KC + k] + g_bhist[(b0 + 3) * KC + k];
    }
    __syncthreads();
    {
        int k = tid & 63, grp = tid >> 6;
        int s = 0;
        for (int c = grp * 16; c < grp * 16 + 16; ++c) s += chunkh[c * KC + k];
        partial[grp * KC + k] = s;
    }
    __syncthreads();
    if (tid == 0) {
        int acc = 0;
        for (int k = 0; k < KC; ++k) {
            pre[k] = acc;
            acc += partial[k] + partial[KC + k] + partial[2 * KC + k] + partial[3 * KC + k];
        }
        pre[KC] = acc;
        g_tickA = 0;
    }
    __syncthreads();
    if (tid <= KC) g_off[tid] = pre[tid];
    {
        int k = tid & 63, cg = tid >> 6;
        int run = pre[k];
        for (int g2 = 0; g2 < cg; ++g2) run += partial[g2 * KC + k];
        for (int c = cg * 16; c < cg * 16 + 16; ++c) {
            g_boff2[c * KC + k] = run;
            run += chunkh[c * KC + k];
        }
    }
}

// ============ pass C: counting-sort scatter ============
__global__ __launch_bounds__(256) void k_passC() {
    __shared__ int cnt[KC];
    __shared__ int base[KC];
    int t = threadIdx.x, b = blockIdx.x;
    if (t < KC) { cnt[t] = 0; base[t] = g_boff2[b * KC + t]; }
    __syncthreads();
    int n = b * 256 + t;
    int a = g_assign[n];
    int r = atomicAdd(&cnt[a], 1);
    g_sorted[base[a] + r] = n;
}

// ============ pass E: raw-moment SYRK + per-dim sums, cp.async pipeline, upper triangle ============
__global__ __launch_bounds__(256) void k_passE(const float* __restrict__ x) {
    __shared__ float xs[STG][NBE][DD];    // 16 KB
    __shared__ int offs[KC + 1];
    __shared__ int sidx[CHE2];
    int tid = threadIdx.x;

    int p0 = blockIdx.x * CHE2;
    if (p0 >= BN) return;                 // uniform per-block
    int p1 = min(p0 + CHE2, BN);

    if (tid <= KC) offs[tid] = g_off[tid];
    for (int i = tid; i < p1 - p0; i += 256) sidx[i] = g_sorted[p0 + i];

    // roles: warp0 lanes 0-15 -> diag tiles (full batch); 240 lanes -> 120 upper tiles x 2 halves
    int w = tid >> 5, l = tid & 31;
    int ti, tj, sBeg, sEnd;
    if (w == 0 && l < 16) {
        ti = l; tj = l; sBeg = 0; sEnd = NBE;
    } else {
        int slot = (w == 0) ? (l - 16) : (16 + (w - 1) * 32 + l);
        int h = (slot >= 120) ? 1 : 0;
        int u = slot - h * 120;
        int a = 0, cnt = 15, rem = u;
        while (rem >= cnt) { rem -= cnt; a++; cnt--; }
        ti = a; tj = a + 1 + rem;
        sBeg = h * (NBE / 2); sEnd = sBeg + NBE / 2;
    }
    int ri = ti * 8, cj = tj * 8;

    int myS = tid >> 5;          // sample slot 0..7 (for cp.async issue)
    int myQ = tid & 31;          // float4 index 0..31
    int sumD = tid & 127;        // dim owned for mean-sum accumulation
    int sumS0 = (tid >> 7) * (NBE / 2);   // half of the batch this thread sums
    __syncthreads();

    int k = 0;
    while (k < KC && offs[k + 1] <= p0) k++;
    for (; k < KC && offs[k] < p1; ++k) {
        int s0 = max(offs[k], p0), s1 = min(offs[k + 1], p1);
        if (s1 <= s0) continue;

        float acc[8][8];
#pragma unroll
        for (int i = 0; i < 8; ++i)
#pragma unroll
            for (int j = 0; j < 8; ++j) acc[i][j] = 0.f;
        float sumAcc = 0.f;

        int nb = (s1 - s0 + NBE - 1) / NBE;

        // prologue: issue batches 0..STG-1 (guarded), always commit
#pragma unroll
        for (int pb = 0; pb < STG; ++pb) {
            int base = s0 + pb * NBE;
            if (base < s1) {
                int pos = base + myS;
                float* dgen = &xs[pb][myS][myQ * 4];
                if (pos < s1) {
                    const float* src = x + (size_t)sidx[pos - p0] * DD + myQ * 4;
                    unsigned int dst = (unsigned int)__cvta_generic_to_shared(dgen);
                    CP_ASYNC16(dst, src);
                } else {
                    *(float4*)dgen = make_float4(0.f, 0.f, 0.f, 0.f);
                }
            }
            CP_COMMIT();
        }

        for (int bi = 0; bi < nb; ++bi) {
            CP_WAIT3();
            __syncthreads();
            int st = bi & (STG - 1);
            for (int s = sBeg; s < sEnd; ++s) {
                float rv[8], cv[8];
#pragma unroll
                for (int i = 0; i < 8; ++i) rv[i] = xs[st][s][ri + i];
#pragma unroll
                for (int j = 0; j < 8; ++j) cv[j] = xs[st][s][cj + j];
#pragma unroll
                for (int i = 0; i < 8; ++i)
#pragma unroll
                    for (int j = 0; j < 8; ++j) acc[i][j] = fmaf(rv[i], cv[j], acc[i][j]);
            }
            // per-dim mean sums (zero-padded tails contribute 0)
#pragma unroll
            for (int s = 0; s < NBE / 2; ++s) sumAcc += xs[st][sumS0 + s][sumD];
            __syncthreads();
            // issue batch bi+STG into the just-freed stage
            {
                int base = s0 + (bi + STG) * NBE;
                if (base < s1) {
                    int pos = base + myS;
                    float* dgen = &xs[st][myS][myQ * 4];
                    if (pos < s1) {
                        const float* src = x + (size_t)sidx[pos - p0] * DD + myQ * 4;
                        unsigned int dst = (unsigned int)__cvta_generic_to_shared(dgen);
                        CP_ASYNC16(dst, src);
                    } else {
                        *(float4*)dgen = make_float4(0.f, 0.f, 0.f, 0.f);
                    }
                }
                CP_COMMIT();
            }
        }

        float* cb = g_cov + (size_t)k * DD * DD;
#pragma unroll
        for (int i = 0; i < 8; ++i)
#pragma unroll
            for (int j = 0; j < 8; ++j)
                atomicAdd(&cb[(ri + i) * DD + cj + j], acc[i][j]);
        if (sumAcc != 0.f) atomicAdd(&g_meansum[k * DD + sumD], sumAcc);
    }
}

// ============ pass F1: covar from raw moments + mean_mse + (ticket) final scalars ============
__global__ __launch_bounds__(256) void k_passF1(const float* __restrict__ cen,
                                                float* __restrict__ out_scalars) {
    __shared__ float rd[256], ro[256];
    __shared__ float Trow[DD];
    __shared__ int isLast;
    int k = blockIdx.x, tid = threadIdx.x;
    float w = (float)(g_off[k + 1] - g_off[k]);
    float inv = 1.f / (w + 1e-7f);
    float c2 = inv * (2.f - w * inv);     // exact epsilon-aware cross-term factor
    if (tid < DD) Trow[tid] = g_meansum[k * DD + tid];
    __syncthreads();

    // mean_mse partial: m = T*inv ; w * sum_d (m - cen)^2
    {
        float md = 0.f;
        if (tid < DD) {
            float m = Trow[tid] * inv;
            float d = m - cen[k * DD + tid];
            md = d * d;
        }
        rd[tid] = md;
        __syncthreads();
        for (int s = 128; s > 0; s >>= 1) {
            if (tid < s) rd[tid] += rd[tid + s];
            __syncthreads();
        }
        if (tid == 0) g_meanpart[k] = w * rd[0];
        __syncthreads();
    }

    const float* cb = g_cov + (size_t)k * DD * DD;
    float ds = 0.f, os = 0.f;
    for (int i = tid; i < DD * DD; i += 256) {
        int d = i >> 7, e = i & 127;
        if (e < d) continue;
        float S = cb[i];
        float cv = (S - c2 * Trow[d] * Trow[e]) * inv;
        if (d == e) { float t2 = cv - 1.f; ds += t2 * t2; }
        else os += cv * cv;
    }
    rd[tid] = ds; ro[tid] = os;
    __syncthreads();
    for (int s = 128; s > 0; s >>= 1) {
        if (tid < s) { rd[tid] += rd[tid + s]; ro[tid] += ro[tid + s]; }
        __syncthreads();
    }
    if (tid == 0) {
        float bd = (float)BN * (float)DD;
        g_covpart[k] = w * rd[0] / bd + 2.f * w * ro[0] / (bd * (float)(DD - 1));
    }
    __threadfence();
    __syncthreads();
    if (tid == 0) {
        int v = atomicAdd(&g_tickF, 1);
        isLast = (v == gridDim.x - 1) ? 1 : 0;
    }
    __syncthreads();
    if (!isLast) return;

    float cs2 = (tid < KC) ? g_covpart[tid] : 0.f;
    float ms2 = (tid < KC) ? g_meanpart[tid] : 0.f;
#pragma unroll
    for (int m = 16; m > 0; m >>= 1) {
        cs2 += __shfl_xor_sync(0xffffffffu, cs2, m);
        ms2 += __shfl_xor_sync(0xffffffffu, ms2, m);
    }
    if ((tid & 31) == 0) { rd[tid >> 5] = cs2; ro[tid >> 5] = ms2; }
    __syncthreads();
    if (tid == 0) {
        out_scalars[0] = (ro[0] + ro[1]) / ((float)BN * (float)DD);
        out_scalars[1] = rd[0] + rd[1];
        g_tickF = 0;
    }
}

extern "C" void kernel_launch(void* const* d_in, const int* in_sizes, int n_in,
                              void* d_out, int out_size) {
    const float* x = (const float*)d_in[0];
    const float* c = (const float*)d_in[1];
    float* out = (float*)d_out;

    k_passA<<<NBLK_A, 256>>>(x, c, out);
    k_passC<<<64, 256>>>();
    k_passE<<<NBLK_E, 256>>>(x);
    k_passF1<<<KC, 256>>>(c, out + (out_size - 2));
}

// round 11
// speedup vs baseline: 1.6131x; 1.0993x over previous
#include <cuda_runtime.h>
#include <cstdint>
#include <math.h>

#define BN 16384
#define KC 64
#define DD 128
#define NBLK_A 256
#define CSTR 92   // cs row stride in words (group q at q*12, 8 floats per group)

#define NBE 8          // samples per passE batch
#define STG 4          // cp.async pipeline stages
#define NBLK_E 296
#define CHE2 56

__device__ int   g_assign[BN];
__device__ int   g_bhist[NBLK_A * KC];
__device__ int   g_boff2[64 * KC];
__device__ int   g_off[KC + 1];
__device__ int   g_sorted[BN];
__device__ float g_meansum[KC * DD];
__device__ float g_cs_acc, g_ms_acc;
__device__ float g_cov[KC * DD * DD];
__device__ int   g_tickA, g_tickF;

#define CP_ASYNC16(dst, src) \
    asm volatile("cp.async.cg.shared.global [%0], [%1], 16;" :: "r"(dst), "l"(src))
#define CP_COMMIT() asm volatile("cp.async.commit_group;")
#define CP_WAIT3()  asm volatile("cp.async.wait_group 3;")

// ============ pass A: zero scratch + dist/log_resp/argmin + hist + (ticket) prefix ============
__global__ __launch_bounds__(256) void k_passA(const float* __restrict__ x,
                                               const float* __restrict__ cen,
                                               float* __restrict__ out) {
    __shared__ float cs[DD * CSTR];
    __shared__ float cn2s[KC];
    __shared__ int hist_s[KC];
    __shared__ int isLast;
    int tid = threadIdx.x;

    {   // zero g_cov / g_meansum slices + scalar accumulators
        float4 z = make_float4(0.f, 0.f, 0.f, 0.f);
        float4* cz = ((float4*)g_cov) + (size_t)blockIdx.x * 1024;
        for (int i = tid; i < 1024; i += 256) cz[i] = z;
        if (tid < 8) ((float4*)g_meansum)[blockIdx.x * 8 + tid] = z;
        if (blockIdx.x == 0 && tid == 0) { g_cs_acc = 0.f; g_ms_acc = 0.f; }
    }

    if (tid < KC) hist_s[tid] = 0;
    for (int i = tid; i < KC * DD; i += 256) {
        int k = i >> 7, d = i & 127;
        cs[d * CSTR + (k >> 3) * 12 + (k & 7)] = cen[i];
    }
    if (tid < KC) {
        const float* cr = cen + tid * DD;
        float s0 = 0.f, s1 = 0.f, s2 = 0.f, s3 = 0.f;
        for (int d = 0; d < DD; d += 4) {
            s0 += cr[d] * cr[d];
            s1 += cr[d + 1] * cr[d + 1];
            s2 += cr[d + 2] * cr[d + 2];
            s3 += cr[d + 3] * cr[d + 3];
        }
        cn2s[tid] = (s0 + s1) + (s2 + s3);
    }
    __syncthreads();

    int g = blockIdx.x * 256 + tid;
    int q = g & 7;
    int pairI = g >> 3;
    int n0 = pairI * 2, n1 = n0 + 1;

    const float4* x40 = (const float4*)(x + (size_t)n0 * DD);
    const float4* x41 = (const float4*)(x + (size_t)n1 * DD);

    float acc0[8], acc1[8];
#pragma unroll
    for (int kl = 0; kl < 8; ++kl) { acc0[kl] = 0.f; acc1[kl] = 0.f; }
    float xn20 = 0.f, xn21 = 0.f;

#pragma unroll 4
    for (int ch = 0; ch < 16; ++ch) {
        float4 a = x40[ch * 2], b = x40[ch * 2 + 1];
        float4 c4 = x41[ch * 2], d4 = x41[ch * 2 + 1];
        float xa[8] = {a.x, a.y, a.z, a.w, b.x, b.y, b.z, b.w};
        float xb[8] = {c4.x, c4.y, c4.z, c4.w, d4.x, d4.y, d4.z, d4.w};
#pragma unroll
        for (int j = 0; j < 8; ++j) {
            xn20 = fmaf(xa[j], xa[j], xn20);
            xn21 = fmaf(xb[j], xb[j], xn21);
        }
        const float* cp = &cs[(ch * 8) * CSTR + q * 12];
#pragma unroll
        for (int j = 0; j < 8; ++j) {
            float4 ca = *(const float4*)(cp + j * CSTR);
            float4 cb2 = *(const float4*)(cp + j * CSTR + 4);
            acc0[0] = fmaf(xa[j], ca.x, acc0[0]);
            acc0[1] = fmaf(xa[j], ca.y, acc0[1]);
            acc0[2] = fmaf(xa[j], ca.z, acc0[2]);
            acc0[3] = fmaf(xa[j], ca.w, acc0[3]);
            acc0[4] = fmaf(xa[j], cb2.x, acc0[4]);
            acc0[5] = fmaf(xa[j], cb2.y, acc0[5]);
            acc0[6] = fmaf(xa[j], cb2.z, acc0[6]);
            acc0[7] = fmaf(xa[j], cb2.w, acc0[7]);
            acc1[0] = fmaf(xb[j], ca.x, acc1[0]);
            acc1[1] = fmaf(xb[j], ca.y, acc1[1]);
            acc1[2] = fmaf(xb[j], ca.z, acc1[2]);
            acc1[3] = fmaf(xb[j], ca.w, acc1[3]);
            acc1[4] = fmaf(xb[j], cb2.x, acc1[4]);
            acc1[5] = fmaf(xb[j], cb2.y, acc1[5]);
            acc1[6] = fmaf(xb[j], cb2.z, acc1[6]);
            acc1[7] = fmaf(xb[j], cb2.w, acc1[7]);
        }
    }

    float dist0[8], dist1[8];
    float dmin0 = 3.4e38f, dmin1 = 3.4e38f;
    int km0 = 0, km1 = 0;
#pragma unroll
    for (int kl = 0; kl < 8; ++kl) {
        float cn2 = cn2s[q * 8 + kl];
        float dv0 = fmaf(-2.f, acc0[kl], xn20 + cn2);
        float dv1 = fmaf(-2.f, acc1[kl], xn21 + cn2);
        dist0[kl] = dv0; dist1[kl] = dv1;
        if (dv0 < dmin0) { dmin0 = dv0; km0 = q * 8 + kl; }
        if (dv1 < dmin1) { dmin1 = dv1; km1 = q * 8 + kl; }
    }
#pragma unroll
    for (int m = 1; m < 8; m <<= 1) {
        float ov0 = __shfl_xor_sync(0xffffffffu, dmin0, m);
        int   oi0 = __shfl_xor_sync(0xffffffffu, km0, m);
        if (ov0 < dmin0 || (ov0 == dmin0 && oi0 < km0)) { dmin0 = ov0; km0 = oi0; }
        float ov1 = __shfl_xor_sync(0xffffffffu, dmin1, m);
        int   oi1 = __shfl_xor_sync(0xffffffffu, km1, m);
        if (ov1 < dmin1 || (ov1 == dmin1 && oi1 < km1)) { dmin1 = ov1; km1 = oi1; }
    }
    float ls0 = 0.f, ls1 = 0.f;
#pragma unroll
    for (int kl = 0; kl < 8; ++kl) {
        ls0 += __expf(-0.5f * (dist0[kl] - dmin0));
        ls1 += __expf(-0.5f * (dist1[kl] - dmin1));
    }
#pragma unroll
    for (int m = 1; m < 8; m <<= 1) {
        ls0 += __shfl_xor_sync(0xffffffffu, ls0, m);
        ls1 += __shfl_xor_sync(0xffffffffu, ls1, m);
    }
    float lg0 = logf(ls0), lg1 = logf(ls1);
    const float LM = logf(1e-8f);

    float4* o0 = (float4*)(out + (size_t)n0 * KC + q * 8);
    float4* o1 = (float4*)(out + (size_t)n1 * KC + q * 8);
#pragma unroll
    for (int v = 0; v < 2; ++v) {
        float4 r0, r1;
        r0.x = fmaxf(-0.5f * (dist0[4 * v + 0] - dmin0) - lg0, LM);
        r0.y = fmaxf(-0.5f * (dist0[4 * v + 1] - dmin0) - lg0, LM);
        r0.z = fmaxf(-0.5f * (dist0[4 * v + 2] - dmin0) - lg0, LM);
        r0.w = fmaxf(-0.5f * (dist0[4 * v + 3] - dmin0) - lg0, LM);
        r1.x = fmaxf(-0.5f * (dist1[4 * v + 0] - dmin1) - lg1, LM);
        r1.y = fmaxf(-0.5f * (dist1[4 * v + 1] - dmin1) - lg1, LM);
        r1.z = fmaxf(-0.5f * (dist1[4 * v + 2] - dmin1) - lg1, LM);
        r1.w = fmaxf(-0.5f * (dist1[4 * v + 3] - dmin1) - lg1, LM);
        o0[v] = r0; o1[v] = r1;
    }
    if (q == 0) {
        g_assign[n0] = km0;
        g_assign[n1] = km1;
        atomicAdd(&hist_s[km0], 1);
        atomicAdd(&hist_s[km1], 1);
    }
    __syncthreads();
    if (tid < KC) g_bhist[blockIdx.x * KC + tid] = hist_s[tid];

    __threadfence();
    __syncthreads();
    if (tid == 0) {
        int v = atomicAdd(&g_tickA, 1);
        isLast = (v == NBLK_A - 1) ? 1 : 0;
    }
    __syncthreads();
    if (!isLast) return;

    int* ibuf = (int*)cs;
    int* partial = ibuf;           // 4*64
    int* pre = ibuf + 256;         // 65
    int* chunkh = ibuf + 384;      // 64*64

    for (int i = tid; i < 64 * KC; i += 256) {
        int c = i >> 6, k = i & 63;
        int b0 = c * 4;
        chunkh[i] = g_bhist[b0 * KC + k] + g_bhist[(b0 + 1) * KC + k]
                  + g_bhist[(b0 + 2) * KC + k] + g_bhist[(b0 + 3) * KC + k];
    }
    __syncthreads();
    {
        int k = tid & 63, grp = tid >> 6;
        int s = 0;
        for (int c = grp * 16; c < grp * 16 + 16; ++c) s += chunkh[c * KC + k];
        partial[grp * KC + k] = s;
    }
    __syncthreads();
    if (tid == 0) {
        int acc = 0;
        for (int k = 0; k < KC; ++k) {
            pre[k] = acc;
            acc += partial[k] + partial[KC + k] + partial[2 * KC + k] + partial[3 * KC + k];
        }
        pre[KC] = acc;
        g_tickA = 0;
    }
    __syncthreads();
    if (tid <= KC) g_off[tid] = pre[tid];
    {
        int k = tid & 63, cg = tid >> 6;
        int run = pre[k];
        for (int g2 = 0; g2 < cg; ++g2) run += partial[g2 * KC + k];
        for (int c = cg * 16; c < cg * 16 + 16; ++c) {
            g_boff2[c * KC + k] = run;
            run += chunkh[c * KC + k];
        }
    }
}

// ============ pass C: counting-sort scatter ============
__global__ __launch_bounds__(256) void k_passC() {
    __shared__ int cnt[KC];
    __shared__ int base[KC];
    int t = threadIdx.x, b = blockIdx.x;
    if (t < KC) { cnt[t] = 0; base[t] = g_boff2[b * KC + t]; }
    __syncthreads();
    int n = b * 256 + t;
    int a = g_assign[n];
    int r = atomicAdd(&cnt[a], 1);
    g_sorted[base[a] + r] = n;
}

// ============ pass E: raw-moment SYRK + per-dim sums, cp.async pipeline, upper triangle ============
__global__ __launch_bounds__(256) void k_passE(const float* __restrict__ x) {
    __shared__ float xs[STG][NBE][DD];    // 16 KB
    __shared__ int offs[KC + 1];
    __shared__ int sidx[CHE2];
    int tid = threadIdx.x;

    int p0 = blockIdx.x * CHE2;
    if (p0 >= BN) return;                 // uniform per-block
    int p1 = min(p0 + CHE2, BN);

    if (tid <= KC) offs[tid] = g_off[tid];
    for (int i = tid; i < p1 - p0; i += 256) sidx[i] = g_sorted[p0 + i];

    // roles: warp0 lanes 0-15 -> diag tiles (full batch); 240 lanes -> 120 upper tiles x 2 halves
    int w = tid >> 5, l = tid & 31;
    int ti, tj, sBeg, sEnd;
    if (w == 0 && l < 16) {
        ti = l; tj = l; sBeg = 0; sEnd = NBE;
    } else {
        int slot = (w == 0) ? (l - 16) : (16 + (w - 1) * 32 + l);
        int h = (slot >= 120) ? 1 : 0;
        int u = slot - h * 120;
        int a = 0, cnt = 15, rem = u;
        while (rem >= cnt) { rem -= cnt; a++; cnt--; }
        ti = a; tj = a + 1 + rem;
        sBeg = h * (NBE / 2); sEnd = sBeg + NBE / 2;
    }
    int ri = ti * 8, cj = tj * 8;

    int myS = tid >> 5;          // sample slot 0..7 (for cp.async issue)
    int myQ = tid & 31;          // float4 index 0..31
    int sumD = tid & 127;        // dim owned for mean-sum accumulation
    int sumS0 = (tid >> 7) * (NBE / 2);   // half of the batch this thread sums
    __syncthreads();

    int k = 0;
    while (k < KC && offs[k + 1] <= p0) k++;
    for (; k < KC && offs[k] < p1; ++k) {
        int s0 = max(offs[k], p0), s1 = min(offs[k + 1], p1);
        if (s1 <= s0) continue;

        float acc[8][8];
#pragma unroll
        for (int i = 0; i < 8; ++i)
#pragma unroll
            for (int j = 0; j < 8; ++j) acc[i][j] = 0.f;
        float sumAcc = 0.f;

        int nb = (s1 - s0 + NBE - 1) / NBE;

        // prologue: issue batches 0..STG-1 (guarded), always commit
#pragma unroll
        for (int pb = 0; pb < STG; ++pb) {
            int base = s0 + pb * NBE;
            if (base < s1) {
                int pos = base + myS;
                float* dgen = &xs[pb][myS][myQ * 4];
                if (pos < s1) {
                    const float* src = x + (size_t)sidx[pos - p0] * DD + myQ * 4;
                    unsigned int dst = (unsigned int)__cvta_generic_to_shared(dgen);
                    CP_ASYNC16(dst, src);
                } else {
                    *(float4*)dgen = make_float4(0.f, 0.f, 0.f, 0.f);
                }
            }
            CP_COMMIT();
        }

        for (int bi = 0; bi < nb; ++bi) {
            CP_WAIT3();
            __syncthreads();
            int st = bi & (STG - 1);
            for (int s = sBeg; s < sEnd; ++s) {
                float rv[8], cv[8];
#pragma unroll
                for (int i = 0; i < 8; ++i) rv[i] = xs[st][s][ri + i];
#pragma unroll
                for (int j = 0; j < 8; ++j) cv[j] = xs[st][s][cj + j];
#pragma unroll
                for (int i = 0; i < 8; ++i)
#pragma unroll
                    for (int j = 0; j < 8; ++j) acc[i][j] = fmaf(rv[i], cv[j], acc[i][j]);
            }
            // per-dim mean sums (zero-padded tails contribute 0)
#pragma unroll
            for (int s = 0; s < NBE / 2; ++s) sumAcc += xs[st][sumS0 + s][sumD];
            __syncthreads();
            // issue batch bi+STG into the just-freed stage
            {
                int base = s0 + (bi + STG) * NBE;
                if (base < s1) {
                    int pos = base + myS;
                    float* dgen = &xs[st][myS][myQ * 4];
                    if (pos < s1) {
                        const float* src = x + (size_t)sidx[pos - p0] * DD + myQ * 4;
                        unsigned int dst = (unsigned int)__cvta_generic_to_shared(dgen);
                        CP_ASYNC16(dst, src);
                    } else {
                        *(float4*)dgen = make_float4(0.f, 0.f, 0.f, 0.f);
                    }
                }
                CP_COMMIT();
            }
        }

        float* cb = g_cov + (size_t)k * DD * DD;
#pragma unroll
        for (int i = 0; i < 8; ++i)
#pragma unroll
            for (int j = 0; j < 8; ++j)
                atomicAdd(&cb[(ri + i) * DD + cj + j], acc[i][j]);
        if (sumAcc != 0.f) atomicAdd(&g_meansum[k * DD + sumD], sumAcc);
    }
}

// ============ pass F1: 4 blocks/cluster slab reduction + (ticket) final scalars ============
__global__ __launch_bounds__(256) void k_passF1(const float* __restrict__ cen,
                                                float* __restrict__ out_scalars) {
    __shared__ float Trow[DD];
    __shared__ float rA[8], rB[8], rC[8];
    __shared__ int isLast;
    int b = blockIdx.x, tid = threadIdx.x;
    int k = b >> 2, r = b & 3;          // cluster, row-slab (32 rows)
    float w = (float)(g_off[k + 1] - g_off[k]);
    float inv = 1.f / (w + 1e-7f);
    float c2 = inv * (2.f - w * inv);   // exact epsilon-aware cross-term factor
    if (tid < DD) Trow[tid] = g_meansum[k * DD + tid];
    __syncthreads();

    float ds = 0.f, os = 0.f;
    const float4* cb4 = (const float4*)(g_cov + (size_t)k * DD * DD + (size_t)r * 32 * DD);
#pragma unroll
    for (int it = 0; it < 4; ++it) {
        int i4 = it * 256 + tid;        // 0..1023
        int d = r * 32 + (i4 >> 5);     // global row
        int e0 = (i4 & 31) << 2;        // col start
        float4 S = cb4[i4];
        float Td = Trow[d];
        float v[4] = {S.x, S.y, S.z, S.w};
#pragma unroll
        for (int j = 0; j < 4; ++j) {
            int e = e0 + j;
            if (e < d) continue;
            float cv = (v[j] - c2 * Td * Trow[e]) * inv;
            if (e == d) { float t2 = cv - 1.f; ds += t2 * t2; }
            else os += cv * cv;
        }
    }
    float msp = 0.f;
    if (r == 0 && tid < DD) {
        float m = Trow[tid] * inv;
        float dmc = m - cen[k * DD + tid];
        msp = w * dmc * dmc;
    }
#pragma unroll
    for (int m = 16; m > 0; m >>= 1) {
        ds  += __shfl_xor_sync(0xffffffffu, ds, m);
        os  += __shfl_xor_sync(0xffffffffu, os, m);
        msp += __shfl_xor_sync(0xffffffffu, msp, m);
    }
    if ((tid & 31) == 0) { rA[tid >> 5] = ds; rB[tid >> 5] = os; rC[tid >> 5] = msp; }
    __syncthreads();
    if (tid == 0) {
        float dsum = 0.f, osum = 0.f, msum = 0.f;
#pragma unroll
        for (int i = 0; i < 8; ++i) { dsum += rA[i]; osum += rB[i]; msum += rC[i]; }
        float bd = (float)BN * (float)DD;
        float contrib = w * dsum / bd + 2.f * w * osum / (bd * (float)(DD - 1));
        atomicAdd(&g_cs_acc, contrib);
        if (r == 0) atomicAdd(&g_ms_acc, msum);
    }
    __threadfence();
    __syncthreads();
    if (tid == 0) {
        int v = atomicAdd(&g_tickF, 1);
        isLast = (v == gridDim.x - 1) ? 1 : 0;
    }
    __syncthreads();
    if (!isLast) return;
    if (tid == 0) {
        out_scalars[0] = g_ms_acc / ((float)BN * (float)DD);
        out_scalars[1] = g_cs_acc;
        g_tickF = 0;
    }
}

extern "C" void kernel_launch(void* const* d_in, const int* in_sizes, int n_in,
                              void* d_out, int out_size) {
    const float* x = (const float*)d_in[0];
    const float* c = (const float*)d_in[1];
    float* out = (float*)d_out;

    k_passA<<<NBLK_A, 256>>>(x, c, out);
    k_passC<<<64, 256>>>();
    k_passE<<<NBLK_E, 256>>>(x);
    k_passF1<<<KC * 4, 256>>>(c, out + (out_size - 2));
}

// round 12
// speedup vs baseline: 1.6166x; 1.0022x over previous
#include <cuda_runtime.h>
#include <cstdint>
#include <math.h>

#define BN 16384
#define KC 64
#define DD 128
#define NBLK_A 256
#define CSTR 92   // cs row stride in words (group q at q*12, 8 floats per group)

#define NBE 8          // samples per passE batch
#define STG 4          // cp.async pipeline stages
#define NBLK_E 296
#define CHE2 56
#define NCH 128        // passC chunks (128 samples each)

__device__ int   g_assign[BN];
__device__ int   g_bhist[NBLK_A * KC];
__device__ int   g_boff2[NCH * KC];
__device__ int   g_off[KC + 1];
__device__ int   g_sorted[BN];
__device__ float g_meansum[KC * DD];
__device__ float g_cs_acc, g_ms_acc;
__device__ float g_cov[KC * DD * DD];
__device__ int   g_tickA, g_tickF;

#define CP_ASYNC16(dst, src) \
    asm volatile("cp.async.cg.shared.global [%0], [%1], 16;" :: "r"(dst), "l"(src))
#define CP_COMMIT() asm volatile("cp.async.commit_group;")
#define CP_WAIT3()  asm volatile("cp.async.wait_group 3;")

// ============ pass A: zero scratch + dist/log_resp/argmin + hist + (ticket) prefix ============
__global__ __launch_bounds__(256) void k_passA(const float* __restrict__ x,
                                               const float* __restrict__ cen,
                                               float* __restrict__ out) {
    __shared__ float cs[DD * CSTR];
    __shared__ float cn2s[KC];
    __shared__ int hist_s[KC];
    __shared__ int isLast;
    int tid = threadIdx.x;

    {   // zero g_cov / g_meansum slices + scalar accumulators
        float4 z = make_float4(0.f, 0.f, 0.f, 0.f);
        float4* cz = ((float4*)g_cov) + (size_t)blockIdx.x * 1024;
        for (int i = tid; i < 1024; i += 256) cz[i] = z;
        if (tid < 8) ((float4*)g_meansum)[blockIdx.x * 8 + tid] = z;
        if (blockIdx.x == 0 && tid == 0) { g_cs_acc = 0.f; g_ms_acc = 0.f; }
    }

    if (tid < KC) hist_s[tid] = 0;
    for (int i = tid; i < KC * DD; i += 256) {
        int k = i >> 7, d = i & 127;
        cs[d * CSTR + (k >> 3) * 12 + (k & 7)] = cen[i];
    }
    if (tid < KC) {
        const float* cr = cen + tid * DD;
        float s0 = 0.f, s1 = 0.f, s2 = 0.f, s3 = 0.f;
        for (int d = 0; d < DD; d += 4) {
            s0 += cr[d] * cr[d];
            s1 += cr[d + 1] * cr[d + 1];
            s2 += cr[d + 2] * cr[d + 2];
            s3 += cr[d + 3] * cr[d + 3];
        }
        cn2s[tid] = (s0 + s1) + (s2 + s3);
    }
    __syncthreads();

    int g = blockIdx.x * 256 + tid;
    int q = g & 7;
    int pairI = g >> 3;
    int n0 = pairI * 2, n1 = n0 + 1;

    const float4* x40 = (const float4*)(x + (size_t)n0 * DD);
    const float4* x41 = (const float4*)(x + (size_t)n1 * DD);

    float acc0[8], acc1[8];
#pragma unroll
    for (int kl = 0; kl < 8; ++kl) { acc0[kl] = 0.f; acc1[kl] = 0.f; }
    float xn20 = 0.f, xn21 = 0.f;

#pragma unroll 4
    for (int ch = 0; ch < 16; ++ch) {
        float4 a = x40[ch * 2], b = x40[ch * 2 + 1];
        float4 c4 = x41[ch * 2], d4 = x41[ch * 2 + 1];
        float xa[8] = {a.x, a.y, a.z, a.w, b.x, b.y, b.z, b.w};
        float xb[8] = {c4.x, c4.y, c4.z, c4.w, d4.x, d4.y, d4.z, d4.w};
#pragma unroll
        for (int j = 0; j < 8; ++j) {
            xn20 = fmaf(xa[j], xa[j], xn20);
            xn21 = fmaf(xb[j], xb[j], xn21);
        }
        const float* cp = &cs[(ch * 8) * CSTR + q * 12];
#pragma unroll
        for (int j = 0; j < 8; ++j) {
            float4 ca = *(const float4*)(cp + j * CSTR);
            float4 cb2 = *(const float4*)(cp + j * CSTR + 4);
            acc0[0] = fmaf(xa[j], ca.x, acc0[0]);
            acc0[1] = fmaf(xa[j], ca.y, acc0[1]);
            acc0[2] = fmaf(xa[j], ca.z, acc0[2]);
            acc0[3] = fmaf(xa[j], ca.w, acc0[3]);
            acc0[4] = fmaf(xa[j], cb2.x, acc0[4]);
            acc0[5] = fmaf(xa[j], cb2.y, acc0[5]);
            acc0[6] = fmaf(xa[j], cb2.z, acc0[6]);
            acc0[7] = fmaf(xa[j], cb2.w, acc0[7]);
            acc1[0] = fmaf(xb[j], ca.x, acc1[0]);
            acc1[1] = fmaf(xb[j], ca.y, acc1[1]);
            acc1[2] = fmaf(xb[j], ca.z, acc1[2]);
            acc1[3] = fmaf(xb[j], ca.w, acc1[3]);
            acc1[4] = fmaf(xb[j], cb2.x, acc1[4]);
            acc1[5] = fmaf(xb[j], cb2.y, acc1[5]);
            acc1[6] = fmaf(xb[j], cb2.z, acc1[6]);
            acc1[7] = fmaf(xb[j], cb2.w, acc1[7]);
        }
    }

    float dist0[8], dist1[8];
    float dmin0 = 3.4e38f, dmin1 = 3.4e38f;
    int km0 = 0, km1 = 0;
#pragma unroll
    for (int kl = 0; kl < 8; ++kl) {
        float cn2 = cn2s[q * 8 + kl];
        float dv0 = fmaf(-2.f, acc0[kl], xn20 + cn2);
        float dv1 = fmaf(-2.f, acc1[kl], xn21 + cn2);
        dist0[kl] = dv0; dist1[kl] = dv1;
        if (dv0 < dmin0) { dmin0 = dv0; km0 = q * 8 + kl; }
        if (dv1 < dmin1) { dmin1 = dv1; km1 = q * 8 + kl; }
    }
#pragma unroll
    for (int m = 1; m < 8; m <<= 1) {
        float ov0 = __shfl_xor_sync(0xffffffffu, dmin0, m);
        int   oi0 = __shfl_xor_sync(0xffffffffu, km0, m);
        if (ov0 < dmin0 || (ov0 == dmin0 && oi0 < km0)) { dmin0 = ov0; km0 = oi0; }
        float ov1 = __shfl_xor_sync(0xffffffffu, dmin1, m);
        int   oi1 = __shfl_xor_sync(0xffffffffu, km1, m);
        if (ov1 < dmin1 || (ov1 == dmin1 && oi1 < km1)) { dmin1 = ov1; km1 = oi1; }
    }
    float ls0 = 0.f, ls1 = 0.f;
#pragma unroll
    for (int kl = 0; kl < 8; ++kl) {
        ls0 += __expf(-0.5f * (dist0[kl] - dmin0));
        ls1 += __expf(-0.5f * (dist1[kl] - dmin1));
    }
#pragma unroll
    for (int m = 1; m < 8; m <<= 1) {
        ls0 += __shfl_xor_sync(0xffffffffu, ls0, m);
        ls1 += __shfl_xor_sync(0xffffffffu, ls1, m);
    }
    float lg0 = logf(ls0), lg1 = logf(ls1);
    const float LM = logf(1e-8f);

    float4* o0 = (float4*)(out + (size_t)n0 * KC + q * 8);
    float4* o1 = (float4*)(out + (size_t)n1 * KC + q * 8);
#pragma unroll
    for (int v = 0; v < 2; ++v) {
        float4 r0, r1;
        r0.x = fmaxf(-0.5f * (dist0[4 * v + 0] - dmin0) - lg0, LM);
        r0.y = fmaxf(-0.5f * (dist0[4 * v + 1] - dmin0) - lg0, LM);
        r0.z = fmaxf(-0.5f * (dist0[4 * v + 2] - dmin0) - lg0, LM);
        r0.w = fmaxf(-0.5f * (dist0[4 * v + 3] - dmin0) - lg0, LM);
        r1.x = fmaxf(-0.5f * (dist1[4 * v + 0] - dmin1) - lg1, LM);
        r1.y = fmaxf(-0.5f * (dist1[4 * v + 1] - dmin1) - lg1, LM);
        r1.z = fmaxf(-0.5f * (dist1[4 * v + 2] - dmin1) - lg1, LM);
        r1.w = fmaxf(-0.5f * (dist1[4 * v + 3] - dmin1) - lg1, LM);
        o0[v] = r0; o1[v] = r1;
    }
    if (q == 0) {
        g_assign[n0] = km0;
        g_assign[n1] = km1;
        atomicAdd(&hist_s[km0], 1);
        atomicAdd(&hist_s[km1], 1);
    }
    __syncthreads();
    if (tid < KC) g_bhist[blockIdx.x * KC + tid] = hist_s[tid];

    __threadfence();
    __syncthreads();
    if (tid == 0) {
        int v = atomicAdd(&g_tickA, 1);
        isLast = (v == NBLK_A - 1) ? 1 : 0;
    }
    __syncthreads();
    if (!isLast) return;

    int* ibuf = (int*)cs;
    int* partial = ibuf;           // 4*64
    int* pre = ibuf + 256;         // 65
    int* chunkh = ibuf + 384;      // 128*64 ints (32 KB)

    for (int i = tid; i < NCH * KC; i += 256) {
        int c = i >> 6, k = i & 63;
        chunkh[i] = g_bhist[(2 * c) * KC + k] + g_bhist[(2 * c + 1) * KC + k];
    }
    __syncthreads();
    {
        int k = tid & 63, grp = tid >> 6;
        int s = 0;
        for (int c = grp * 32; c < grp * 32 + 32; ++c) s += chunkh[c * KC + k];
        partial[grp * KC + k] = s;
    }
    __syncthreads();
    if (tid == 0) {
        int acc = 0;
        for (int k = 0; k < KC; ++k) {
            pre[k] = acc;
            acc += partial[k] + partial[KC + k] + partial[2 * KC + k] + partial[3 * KC + k];
        }
        pre[KC] = acc;
        g_tickA = 0;
    }
    __syncthreads();
    if (tid <= KC) g_off[tid] = pre[tid];
    {
        int k = tid & 63, cg = tid >> 6;
        int run = pre[k];
        for (int g2 = 0; g2 < cg; ++g2) run += partial[g2 * KC + k];
        for (int c = cg * 32; c < cg * 32 + 32; ++c) {
            g_boff2[c * KC + k] = run;
            run += chunkh[c * KC + k];
        }
    }
}

// ============ pass C: counting-sort scatter, 128 samples/block over 128 blocks ============
__global__ __launch_bounds__(128) void k_passC() {
    __shared__ int cnt[KC];
    __shared__ int base[KC];
    int t = threadIdx.x, b = blockIdx.x;
    if (t < KC) { cnt[t] = 0; base[t] = g_boff2[b * KC + t]; }
    __syncthreads();
    int n = b * 128 + t;
    int a = g_assign[n];
    int r = atomicAdd(&cnt[a], 1);
    g_sorted[base[a] + r] = n;
}

// ============ pass E: raw-moment SYRK + per-dim sums, cp.async pipeline, upper triangle ============
// __launch_bounds__(256, 2): force 2 CTAs/SM (<=124 regs) so co-resident CTAs hide latency.
__global__ __launch_bounds__(256, 2) void k_passE(const float* __restrict__ x) {
    __shared__ float xs[STG][NBE][DD];    // 16 KB
    __shared__ int offs[KC + 1];
    __shared__ int sidx[CHE2];
    int tid = threadIdx.x;

    int p0 = blockIdx.x * CHE2;
    if (p0 >= BN) return;                 // uniform per-block
    int p1 = min(p0 + CHE2, BN);

    if (tid <= KC) offs[tid] = g_off[tid];
    for (int i = tid; i < p1 - p0; i += 256) sidx[i] = g_sorted[p0 + i];

    // roles: warp0 lanes 0-15 -> diag tiles (full batch); 240 lanes -> 120 upper tiles x 2 halves
    int w = tid >> 5, l = tid & 31;
    int ti, tj, sBeg, sEnd;
    if (w == 0 && l < 16) {
        ti = l; tj = l; sBeg = 0; sEnd = NBE;
    } else {
        int slot = (w == 0) ? (l - 16) : (16 + (w - 1) * 32 + l);
        int h = (slot >= 120) ? 1 : 0;
        int u = slot - h * 120;
        int a = 0, cnt = 15, rem = u;
        while (rem >= cnt) { rem -= cnt; a++; cnt--; }
        ti = a; tj = a + 1 + rem;
        sBeg = h * (NBE / 2); sEnd = sBeg + NBE / 2;
    }
    int ri = ti * 8, cj = tj * 8;

    int myS = tid >> 5;          // sample slot 0..7 (for cp.async issue)
    int myQ = tid & 31;          // float4 index 0..31
    int sumD = tid & 127;        // dim owned for mean-sum accumulation
    int sumS0 = (tid >> 7) * (NBE / 2);   // half of the batch this thread sums
    __syncthreads();

    int k = 0;
    while (k < KC && offs[k + 1] <= p0) k++;
    for (; k < KC && offs[k] < p1; ++k) {
        int s0 = max(offs[k], p0), s1 = min(offs[k + 1], p1);
        if (s1 <= s0) continue;

        float acc[8][8];
#pragma unroll
        for (int i = 0; i < 8; ++i)
#pragma unroll
            for (int j = 0; j < 8; ++j) acc[i][j] = 0.f;
        float sumAcc = 0.f;

        int nb = (s1 - s0 + NBE - 1) / NBE;

        // prologue: issue batches 0..STG-1 (guarded), always commit
#pragma unroll
        for (int pb = 0; pb < STG; ++pb) {
            int base = s0 + pb * NBE;
            if (base < s1) {
                int pos = base + myS;
                float* dgen = &xs[pb][myS][myQ * 4];
                if (pos < s1) {
                    const float* src = x + (size_t)sidx[pos - p0] * DD + myQ * 4;
                    unsigned int dst = (unsigned int)__cvta_generic_to_shared(dgen);
                    CP_ASYNC16(dst, src);
                } else {
                    *(float4*)dgen = make_float4(0.f, 0.f, 0.f, 0.f);
                }
            }
            CP_COMMIT();
        }

        for (int bi = 0; bi < nb; ++bi) {
            CP_WAIT3();
            __syncthreads();
            int st = bi & (STG - 1);
            for (int s = sBeg; s < sEnd; ++s) {
                float rv[8], cv[8];
#pragma unroll
                for (int i = 0; i < 8; ++i) rv[i] = xs[st][s][ri + i];
#pragma unroll
                for (int j = 0; j < 8; ++j) cv[j] = xs[st][s][cj + j];
#pragma unroll
                for (int i = 0; i < 8; ++i)
#pragma unroll
                    for (int j = 0; j < 8; ++j) acc[i][j] = fmaf(rv[i], cv[j], acc[i][j]);
            }
            // per-dim mean sums (zero-padded tails contribute 0)
#pragma unroll
            for (int s = 0; s < NBE / 2; ++s) sumAcc += xs[st][sumS0 + s][sumD];
            __syncthreads();
            // issue batch bi+STG into the just-freed stage
            {
                int base = s0 + (bi + STG) * NBE;
                if (base < s1) {
                    int pos = base + myS;
                    float* dgen = &xs[st][myS][myQ * 4];
                    if (pos < s1) {
                        const float* src = x + (size_t)sidx[pos - p0] * DD + myQ * 4;
                        unsigned int dst = (unsigned int)__cvta_generic_to_shared(dgen);
                        CP_ASYNC16(dst, src);
                    } else {
                        *(float4*)dgen = make_float4(0.f, 0.f, 0.f, 0.f);
                    }
                }
                CP_COMMIT();
            }
        }

        float* cb = g_cov + (size_t)k * DD * DD;
#pragma unroll
        for (int i = 0; i < 8; ++i)
#pragma unroll
            for (int j = 0; j < 8; ++j)
                atomicAdd(&cb[(ri + i) * DD + cj + j], acc[i][j]);
        if (sumAcc != 0.f) atomicAdd(&g_meansum[k * DD + sumD], sumAcc);
    }
}

// ============ pass F1: 4 blocks/cluster slab reduction + (ticket) final scalars ============
__global__ __launch_bounds__(256) void k_passF1(const float* __restrict__ cen,
                                                float* __restrict__ out_scalars) {
    __shared__ float Trow[DD];
    __shared__ float rA[8], rB[8], rC[8];
    __shared__ int isLast;
    int b = blockIdx.x, tid = threadIdx.x;
    int k = b >> 2, r = b & 3;          // cluster, row-slab (32 rows)
    float w = (float)(g_off[k + 1] - g_off[k]);
    float inv = 1.f / (w + 1e-7f);
    float c2 = inv * (2.f - w * inv);   // exact epsilon-aware cross-term factor
    if (tid < DD) Trow[tid] = g_meansum[k * DD + tid];
    __syncthreads();

    float ds = 0.f, os = 0.f;
    const float4* cb4 = (const float4*)(g_cov + (size_t)k * DD * DD + (size_t)r * 32 * DD);
#pragma unroll
    for (int it = 0; it < 4; ++it) {
        int i4 = it * 256 + tid;        // 0..1023
        int d = r * 32 + (i4 >> 5);     // global row
        int e0 = (i4 & 31) << 2;        // col start
        float4 S = cb4[i4];
        float Td = Trow[d];
        float v[4] = {S.x, S.y, S.z, S.w};
#pragma unroll
        for (int j = 0; j < 4; ++j) {
            int e = e0 + j;
            if (e < d) continue;
            float cv = (v[j] - c2 * Td * Trow[e]) * inv;
            if (e == d) { float t2 = cv - 1.f; ds += t2 * t2; }
            else os += cv * cv;
        }
    }
    float msp = 0.f;
    if (r == 0 && tid < DD) {
        float m = Trow[tid] * inv;
        float dmc = m - cen[k * DD + tid];
        msp = w * dmc * dmc;
    }
#pragma unroll
    for (int m = 16; m > 0; m >>= 1) {
        ds  += __shfl_xor_sync(0xffffffffu, ds, m);
        os  += __shfl_xor_sync(0xffffffffu, os, m);
        msp += __shfl_xor_sync(0xffffffffu, msp, m);
    }
    if ((tid & 31) == 0) { rA[tid >> 5] = ds; rB[tid >> 5] = os; rC[tid >> 5] = msp; }
    __syncthreads();
    if (tid == 0) {
        float dsum = 0.f, osum = 0.f, msum = 0.f;
#pragma unroll
        for (int i = 0; i < 8; ++i) { dsum += rA[i]; osum += rB[i]; msum += rC[i]; }
        float bd = (float)BN * (float)DD;
        float contrib = w * dsum / bd + 2.f * w * osum / (bd * (float)(DD - 1));
        atomicAdd(&g_cs_acc, contrib);
        if (r == 0) atomicAdd(&g_ms_acc, msum);
    }
    __threadfence();
    __syncthreads();
    if (tid == 0) {
        int v = atomicAdd(&g_tickF, 1);
        isLast = (v == gridDim.x - 1) ? 1 : 0;
    }
    __syncthreads();
    if (!isLast) return;
    if (tid == 0) {
        out_scalars[0] = g_ms_acc / ((float)BN * (float)DD);
        out_scalars[1] = g_cs_acc;
        g_tickF = 0;
    }
}

extern "C" void kernel_launch(void* const* d_in, const int* in_sizes, int n_in,
                              void* d_out, int out_size) {
    const float* x = (const float*)d_in[0];
    const float* c = (const float*)d_in[1];
    float* out = (float*)d_out;

    k_passA<<<NBLK_A, 256>>>(x, c, out);
    k_passC<<<NCH, 128>>>();
    k_passE<<<NBLK_E, 256>>>(x);
    k_passF1<<<KC * 4, 256>>>(c, out + (out_size - 2));
}

// round 13
// speedup vs baseline: 1.6262x; 1.0059x over previous
#include <cuda_runtime.h>
#include <cstdint>
#include <math.h>

#define BN 16384
#define KC 64
#define DD 128
#define NBLK_A 256
#define CSTR 92   // cs row stride in words (group q at q*12, 8 floats per group)

#define NBE 16         // samples per passE batch
#define STG 3          // cp.async pipeline stages
#define NBLK_E 296
#define CHE2 56
#define XSP 132        // padded row stride (floats) for xs
#define NCH 128        // passC chunks (128 samples each)

__device__ int   g_assign[BN];
__device__ int   g_bhist[NBLK_A * KC];
__device__ int   g_boff2[NCH * KC];
__device__ int   g_off[KC + 1];
__device__ int   g_sorted[BN];
__device__ float g_meansum[KC * DD];
__device__ float g_cs_acc, g_ms_acc;
__device__ float g_cov[KC * DD * DD];
__device__ int   g_tickF;

#define CP_ASYNC16(dst, src) \
    asm volatile("cp.async.cg.shared.global [%0], [%1], 16;" :: "r"(dst), "l"(src))
#define CP_COMMIT() asm volatile("cp.async.commit_group;")
#define CP_WAIT2()  asm volatile("cp.async.wait_group 2;")

// ============ pass A: zero scratch + dist/log_resp/argmin + per-block hist ============
__global__ __launch_bounds__(256) void k_passA(const float* __restrict__ x,
                                               const float* __restrict__ cen,
                                               float* __restrict__ out) {
    __shared__ float cs[DD * CSTR];
    __shared__ float cn2s[KC];
    __shared__ int hist_s[KC];
    int tid = threadIdx.x;

    {   // zero g_cov / g_meansum slices + scalar accumulators
        float4 z = make_float4(0.f, 0.f, 0.f, 0.f);
        float4* cz = ((float4*)g_cov) + (size_t)blockIdx.x * 1024;
        for (int i = tid; i < 1024; i += 256) cz[i] = z;
        if (tid < 8) ((float4*)g_meansum)[blockIdx.x * 8 + tid] = z;
        if (blockIdx.x == 0 && tid == 0) { g_cs_acc = 0.f; g_ms_acc = 0.f; }
    }

    if (tid < KC) hist_s[tid] = 0;
    for (int i = tid; i < KC * DD; i += 256) {
        int k = i >> 7, d = i & 127;
        cs[d * CSTR + (k >> 3) * 12 + (k & 7)] = cen[i];
    }
    if (tid < KC) {
        const float* cr = cen + tid * DD;
        float s0 = 0.f, s1 = 0.f, s2 = 0.f, s3 = 0.f;
        for (int d = 0; d < DD; d += 4) {
            s0 += cr[d] * cr[d];
            s1 += cr[d + 1] * cr[d + 1];
            s2 += cr[d + 2] * cr[d + 2];
            s3 += cr[d + 3] * cr[d + 3];
        }
        cn2s[tid] = (s0 + s1) + (s2 + s3);
    }
    __syncthreads();

    int g = blockIdx.x * 256 + tid;
    int q = g & 7;
    int pairI = g >> 3;
    int n0 = pairI * 2, n1 = n0 + 1;

    const float4* x40 = (const float4*)(x + (size_t)n0 * DD);
    const float4* x41 = (const float4*)(x + (size_t)n1 * DD);

    float acc0[8], acc1[8];
#pragma unroll
    for (int kl = 0; kl < 8; ++kl) { acc0[kl] = 0.f; acc1[kl] = 0.f; }
    float xn20 = 0.f, xn21 = 0.f;

#pragma unroll 4
    for (int ch = 0; ch < 16; ++ch) {
        float4 a = x40[ch * 2], b = x40[ch * 2 + 1];
        float4 c4 = x41[ch * 2], d4 = x41[ch * 2 + 1];
        float xa[8] = {a.x, a.y, a.z, a.w, b.x, b.y, b.z, b.w};
        float xb[8] = {c4.x, c4.y, c4.z, c4.w, d4.x, d4.y, d4.z, d4.w};
#pragma unroll
        for (int j = 0; j < 8; ++j) {
            xn20 = fmaf(xa[j], xa[j], xn20);
            xn21 = fmaf(xb[j], xb[j], xn21);
        }
        const float* cp = &cs[(ch * 8) * CSTR + q * 12];
#pragma unroll
        for (int j = 0; j < 8; ++j) {
            float4 ca = *(const float4*)(cp + j * CSTR);
            float4 cb2 = *(const float4*)(cp + j * CSTR + 4);
            acc0[0] = fmaf(xa[j], ca.x, acc0[0]);
            acc0[1] = fmaf(xa[j], ca.y, acc0[1]);
            acc0[2] = fmaf(xa[j], ca.z, acc0[2]);
            acc0[3] = fmaf(xa[j], ca.w, acc0[3]);
            acc0[4] = fmaf(xa[j], cb2.x, acc0[4]);
            acc0[5] = fmaf(xa[j], cb2.y, acc0[5]);
            acc0[6] = fmaf(xa[j], cb2.z, acc0[6]);
            acc0[7] = fmaf(xa[j], cb2.w, acc0[7]);
            acc1[0] = fmaf(xb[j], ca.x, acc1[0]);
            acc1[1] = fmaf(xb[j], ca.y, acc1[1]);
            acc1[2] = fmaf(xb[j], ca.z, acc1[2]);
            acc1[3] = fmaf(xb[j], ca.w, acc1[3]);
            acc1[4] = fmaf(xb[j], cb2.x, acc1[4]);
            acc1[5] = fmaf(xb[j], cb2.y, acc1[5]);
            acc1[6] = fmaf(xb[j], cb2.z, acc1[6]);
            acc1[7] = fmaf(xb[j], cb2.w, acc1[7]);
        }
    }

    float dist0[8], dist1[8];
    float dmin0 = 3.4e38f, dmin1 = 3.4e38f;
    int km0 = 0, km1 = 0;
#pragma unroll
    for (int kl = 0; kl < 8; ++kl) {
        float cn2 = cn2s[q * 8 + kl];
        float dv0 = fmaf(-2.f, acc0[kl], xn20 + cn2);
        float dv1 = fmaf(-2.f, acc1[kl], xn21 + cn2);
        dist0[kl] = dv0; dist1[kl] = dv1;
        if (dv0 < dmin0) { dmin0 = dv0; km0 = q * 8 + kl; }
        if (dv1 < dmin1) { dmin1 = dv1; km1 = q * 8 + kl; }
    }
#pragma unroll
    for (int m = 1; m < 8; m <<= 1) {
        float ov0 = __shfl_xor_sync(0xffffffffu, dmin0, m);
        int   oi0 = __shfl_xor_sync(0xffffffffu, km0, m);
        if (ov0 < dmin0 || (ov0 == dmin0 && oi0 < km0)) { dmin0 = ov0; km0 = oi0; }
        float ov1 = __shfl_xor_sync(0xffffffffu, dmin1, m);
        int   oi1 = __shfl_xor_sync(0xffffffffu, km1, m);
        if (ov1 < dmin1 || (ov1 == dmin1 && oi1 < km1)) { dmin1 = ov1; km1 = oi1; }
    }
    float ls0 = 0.f, ls1 = 0.f;
#pragma unroll
    for (int kl = 0; kl < 8; ++kl) {
        ls0 += __expf(-0.5f * (dist0[kl] - dmin0));
        ls1 += __expf(-0.5f * (dist1[kl] - dmin1));
    }
#pragma unroll
    for (int m = 1; m < 8; m <<= 1) {
        ls0 += __shfl_xor_sync(0xffffffffu, ls0, m);
        ls1 += __shfl_xor_sync(0xffffffffu, ls1, m);
    }
    float lg0 = logf(ls0), lg1 = logf(ls1);
    const float LM = logf(1e-8f);

    float4* o0 = (float4*)(out + (size_t)n0 * KC + q * 8);
    float4* o1 = (float4*)(out + (size_t)n1 * KC + q * 8);
#pragma unroll
    for (int v = 0; v < 2; ++v) {
        float4 r0, r1;
        r0.x = fmaxf(-0.5f * (dist0[4 * v + 0] - dmin0) - lg0, LM);
        r0.y = fmaxf(-0.5f * (dist0[4 * v + 1] - dmin0) - lg0, LM);
        r0.z = fmaxf(-0.5f * (dist0[4 * v + 2] - dmin0) - lg0, LM);
        r0.w = fmaxf(-0.5f * (dist0[4 * v + 3] - dmin0) - lg0, LM);
        r1.x = fmaxf(-0.5f * (dist1[4 * v + 0] - dmin1) - lg1, LM);
        r1.y = fmaxf(-0.5f * (dist1[4 * v + 1] - dmin1) - lg1, LM);
        r1.z = fmaxf(-0.5f * (dist1[4 * v + 2] - dmin1) - lg1, LM);
        r1.w = fmaxf(-0.5f * (dist1[4 * v + 3] - dmin1) - lg1, LM);
        o0[v] = r0; o1[v] = r1;
    }
    if (q == 0) {
        g_assign[n0] = km0;
        g_assign[n1] = km1;
        atomicAdd(&hist_s[km0], 1);
        atomicAdd(&hist_s[km1], 1);
    }
    __syncthreads();
    if (tid < KC) g_bhist[blockIdx.x * KC + tid] = hist_s[tid];
}

// ============ pass B: totals + prefix + per-chunk scatter offsets (1 block) ============
__global__ __launch_bounds__(256) void k_passB() {
    __shared__ int chunkh[NCH * KC];   // 32 KB
    __shared__ int partial[4 * KC];
    __shared__ int pre[KC + 1];
    int tid = threadIdx.x;

    for (int i = tid; i < NCH * KC; i += 256) {
        int c = i >> 6, k = i & 63;
        chunkh[i] = g_bhist[(2 * c) * KC + k] + g_bhist[(2 * c + 1) * KC + k];
    }
    __syncthreads();
    {
        int k = tid & 63, grp = tid >> 6;
        int s = 0;
        for (int c = grp * 32; c < grp * 32 + 32; ++c) s += chunkh[c * KC + k];
        partial[grp * KC + k] = s;
    }
    __syncthreads();
    if (tid == 0) {
        int acc = 0;
        for (int k = 0; k < KC; ++k) {
            pre[k] = acc;
            acc += partial[k] + partial[KC + k] + partial[2 * KC + k] + partial[3 * KC + k];
        }
        pre[KC] = acc;
    }
    __syncthreads();
    if (tid <= KC) g_off[tid] = pre[tid];
    {
        int k = tid & 63, cg = tid >> 6;
        int run = pre[k];
        for (int g2 = 0; g2 < cg; ++g2) run += partial[g2 * KC + k];
        for (int c = cg * 32; c < cg * 32 + 32; ++c) {
            g_boff2[c * KC + k] = run;
            run += chunkh[c * KC + k];
        }
    }
}

// ============ pass C: counting-sort scatter, 128 samples/block over 128 blocks ============
__global__ __launch_bounds__(128) void k_passC() {
    __shared__ int cnt[KC];
    __shared__ int base[KC];
    int t = threadIdx.x, b = blockIdx.x;
    if (t < KC) { cnt[t] = 0; base[t] = g_boff2[b * KC + t]; }
    __syncthreads();
    int n = b * 128 + t;
    int a = g_assign[n];
    int r = atomicAdd(&cnt[a], 1);
    g_sorted[base[a] + r] = n;
}

// ============ pass E: raw-moment SYRK + per-dim sums; 16-sample batches, 3-stage cp.async ============
__global__ __launch_bounds__(256, 2) void k_passE(const float* __restrict__ x) {
    __shared__ float xs[STG][NBE][XSP];   // ~24.8 KB
    __shared__ int offs[KC + 1];
    __shared__ int sidx[CHE2];
    int tid = threadIdx.x;

    int p0 = blockIdx.x * CHE2;
    if (p0 >= BN) return;                 // uniform per-block
    int p1 = min(p0 + CHE2, BN);

    if (tid <= KC) offs[tid] = g_off[tid];
    for (int i = tid; i < p1 - p0; i += 256) sidx[i] = g_sorted[p0 + i];

    // roles: warp0 lanes 0-15 -> 16 diag tiles (full 16-sample batch);
    //        240 lanes -> 120 upper tiles x 2 batch-halves (8 samples each).
    int w = tid >> 5, l = tid & 31;
    int ti, tj, sBeg, sEnd;
    if (w == 0 && l < 16) {
        ti = l; tj = l; sBeg = 0; sEnd = NBE;
    } else {
        int slot = (w == 0) ? (l - 16) : (16 + (w - 1) * 32 + l);
        int h = (slot >= 120) ? 1 : 0;
        int u = slot - h * 120;
        int a = 0, cnt = 15, rem = u;
        while (rem >= cnt) { rem -= cnt; a++; cnt--; }
        ti = a; tj = a + 1 + rem;
        sBeg = h * (NBE / 2); sEnd = sBeg + NBE / 2;
    }
    int ri = ti * 8, cj = tj * 8;

    int myS = tid >> 4;          // sample slot 0..15 (for cp.async issue)
    int myQ = tid & 15;          // base float4 index; thread also loads myQ+16
    int sumD = tid & 127;        // dim owned for mean-sum accumulation
    int sumS0 = (tid >> 7) * (NBE / 2);   // half of the batch this thread sums
    __syncthreads();

    int k = 0;
    while (k < KC && offs[k + 1] <= p0) k++;
    for (; k < KC && offs[k] < p1; ++k) {
        int s0 = max(offs[k], p0), s1 = min(offs[k + 1], p1);
        if (s1 <= s0) continue;

        float acc[8][8];
#pragma unroll
        for (int i = 0; i < 8; ++i)
#pragma unroll
            for (int j = 0; j < 8; ++j) acc[i][j] = 0.f;
        float sumAcc = 0.f;

        int nb = (s1 - s0 + NBE - 1) / NBE;

        // prologue: issue batches 0..STG-1 (guarded), always commit
#pragma unroll
        for (int pb = 0; pb < STG; ++pb) {
            int base = s0 + pb * NBE;
            if (base < s1) {
                int pos = base + myS;
                float* d0 = &xs[pb][myS][myQ * 4];
                float* d1 = &xs[pb][myS][(myQ + 16) * 4];
                if (pos < s1) {
                    const float* src = x + (size_t)sidx[pos - p0] * DD;
                    CP_ASYNC16((unsigned int)__cvta_generic_to_shared(d0), src + myQ * 4);
                    CP_ASYNC16((unsigned int)__cvta_generic_to_shared(d1), src + (myQ + 16) * 4);
                } else {
                    *(float4*)d0 = make_float4(0.f, 0.f, 0.f, 0.f);
                    *(float4*)d1 = make_float4(0.f, 0.f, 0.f, 0.f);
                }
            }
            CP_COMMIT();
        }

        int st = 0;
        for (int bi = 0; bi < nb; ++bi) {
            CP_WAIT2();
            __syncthreads();
            for (int s = sBeg; s < sEnd; ++s) {
                const float* row = &xs[st][s][0];
                float4 a0 = *(const float4*)(row + ri);
                float4 a1 = *(const float4*)(row + ri + 4);
                float4 b0 = *(const float4*)(row + cj);
                float4 b1 = *(const float4*)(row + cj + 4);
                float rv[8] = {a0.x, a0.y, a0.z, a0.w, a1.x, a1.y, a1.z, a1.w};
                float cv[8] = {b0.x, b0.y, b0.z, b0.w, b1.x, b1.y, b1.z, b1.w};
#pragma unroll
                for (int i = 0; i < 8; ++i)
#pragma unroll
                    for (int j = 0; j < 8; ++j) acc[i][j] = fmaf(rv[i], cv[j], acc[i][j]);
            }
            // per-dim mean sums (zero-padded tails contribute 0)
#pragma unroll
            for (int s = 0; s < NBE / 2; ++s) sumAcc += xs[st][sumS0 + s][sumD];
            __syncthreads();
            // issue batch bi+STG into the just-freed stage
            {
                int base = s0 + (bi + STG) * NBE;
                if (base < s1) {
                    int pos = base + myS;
                    float* d0 = &xs[st][myS][myQ * 4];
                    float* d1 = &xs[st][myS][(myQ + 16) * 4];
                    if (pos < s1) {
                        const float* src = x + (size_t)sidx[pos - p0] * DD;
                        CP_ASYNC16((unsigned int)__cvta_generic_to_shared(d0), src + myQ * 4);
                        CP_ASYNC16((unsigned int)__cvta_generic_to_shared(d1), src + (myQ + 16) * 4);
                    } else {
                        *(float4*)d0 = make_float4(0.f, 0.f, 0.f, 0.f);
                        *(float4*)d1 = make_float4(0.f, 0.f, 0.f, 0.f);
                    }
                }
                CP_COMMIT();
            }
            if (++st == STG) st = 0;
        }

        float* cb = g_cov + (size_t)k * DD * DD;
#pragma unroll
        for (int i = 0; i < 8; ++i)
#pragma unroll
            for (int j = 0; j < 8; ++j)
                atomicAdd(&cb[(ri + i) * DD + cj + j], acc[i][j]);
        if (sumAcc != 0.f) atomicAdd(&g_meansum[k * DD + sumD], sumAcc);
    }
}

// ============ pass F1: 4 blocks/cluster slab reduction + (ticket) final scalars ============
__global__ __launch_bounds__(256) void k_passF1(const float* __restrict__ cen,
                                                float* __restrict__ out_scalars) {
    __shared__ float Trow[DD];
    __shared__ float rA[8], rB[8], rC[8];
    __shared__ int isLast;
    int b = blockIdx.x, tid = threadIdx.x;
    int k = b >> 2, r = b & 3;          // cluster, row-slab (32 rows)
    float w = (float)(g_off[k + 1] - g_off[k]);
    float inv = 1.f / (w + 1e-7f);
    float c2 = inv * (2.f - w * inv);   // exact epsilon-aware cross-term factor
    if (tid < DD) Trow[tid] = g_meansum[k * DD + tid];
    __syncthreads();

    float ds = 0.f, os = 0.f;
    const float4* cb4 = (const float4*)(g_cov + (size_t)k * DD * DD + (size_t)r * 32 * DD);
#pragma unroll
    for (int it = 0; it < 4; ++it) {
        int i4 = it * 256 + tid;        // 0..1023
        int d = r * 32 + (i4 >> 5);     // global row
        int e0 = (i4 & 31) << 2;        // col start
        float4 S = cb4[i4];
        float Td = Trow[d];
        float v[4] = {S.x, S.y, S.z, S.w};
#pragma unroll
        for (int j = 0; j < 4; ++j) {
            int e = e0 + j;
            if (e < d) continue;
            float cv = (v[j] - c2 * Td * Trow[e]) * inv;
            if (e == d) { float t2 = cv - 1.f; ds += t2 * t2; }
            else os += cv * cv;
        }
    }
    float msp = 0.f;
    if (r == 0 && tid < DD) {
        float m = Trow[tid] * inv;
        float dmc = m - cen[k * DD + tid];
        msp = w * dmc * dmc;
    }
#pragma unroll
    for (int m = 16; m > 0; m >>= 1) {
        ds  += __shfl_xor_sync(0xffffffffu, ds, m);
        os  += __shfl_xor_sync(0xffffffffu, os, m);
        msp += __shfl_xor_sync(0xffffffffu, msp, m);
    }
    if ((tid & 31) == 0) { rA[tid >> 5] = ds; rB[tid >> 5] = os; rC[tid >> 5] = msp; }
    __syncthreads();
    if (tid == 0) {
        float dsum = 0.f, osum = 0.f, msum = 0.f;
#pragma unroll
        for (int i = 0; i < 8; ++i) { dsum += rA[i]; osum += rB[i]; msum += rC[i]; }
        float bd = (float)BN * (float)DD;
        float contrib = w * dsum / bd + 2.f * w * osum / (bd * (float)(DD - 1));
        atomicAdd(&g_cs_acc, contrib);
        if (r == 0) atomicAdd(&g_ms_acc, msum);
    }
    __threadfence();
    __syncthreads();
    if (tid == 0) {
        int v = atomicAdd(&g_tickF, 1);
        isLast = (v == gridDim.x - 1) ? 1 : 0;
    }
    __syncthreads();
    if (!isLast) return;
    if (tid == 0) {
        out_scalars[0] = g_ms_acc / ((float)BN * (float)DD);
        out_scalars[1] = g_cs_acc;
        g_tickF = 0;
    }
}

extern "C" void kernel_launch(void* const* d_in, const int* in_sizes, int n_in,
                              void* d_out, int out_size) {
    const float* x = (const float*)d_in[0];
    const float* c = (const float*)d_in[1];
    float* out = (float*)d_out;

    k_passA<<<NBLK_A, 256>>>(x, c, out);
    k_passB<<<1, 256>>>();
    k_passC<<<NCH, 128>>>();
    k_passE<<<NBLK_E, 256>>>(x);   // launch index 3 -> profiled next round
    k_passF1<<<KC * 4, 256>>>(c, out + (out_size - 2));
}

// round 14
// speedup vs baseline: 2.6445x; 1.6261x over previous
#include <cuda_runtime.h>
#include <cstdint>
#include <math.h>

#define BN 16384
#define KC 64
#define DD 128
#define NBLK_A 256
#define CSTR 92   // cs row stride in words (group q at q*12, 8 floats per group)

#define NBE 16         // samples per passE batch
#define STG 3          // cp.async pipeline stages
#define NBLK_E 296
#define CHE2 56
#define XSP 132        // padded row stride (floats) for xs
#define NCH 128        // passC chunks (128 samples each)

__device__ int   g_assign[BN];
__device__ int   g_bhist[NBLK_A * KC];
__device__ int   g_boff2[NCH * KC];
__device__ int   g_off[KC + 1];
__device__ int   g_sorted[BN];
__device__ float g_meansum[KC * DD];
__device__ float g_cs_acc, g_ms_acc;
__device__ float g_cov[KC * DD * DD];
__device__ int   g_tickF;

#define CP_ASYNC16(dst, src) \
    asm volatile("cp.async.cg.shared.global [%0], [%1], 16;" :: "r"(dst), "l"(src))
#define CP_COMMIT() asm volatile("cp.async.commit_group;")
#define CP_WAIT2()  asm volatile("cp.async.wait_group 2;")
#define RED_ADD_V4(ptr, a, b, c, d) \
    asm volatile("red.global.add.v4.f32 [%0], {%1, %2, %3, %4};" \
                 :: "l"(ptr), "f"(a), "f"(b), "f"(c), "f"(d) : "memory")

// ============ pass A: zero scratch + dist/log_resp/argmin + per-block hist ============
__global__ __launch_bounds__(256) void k_passA(const float* __restrict__ x,
                                               const float* __restrict__ cen,
                                               float* __restrict__ out) {
    __shared__ float cs[DD * CSTR];
    __shared__ float cn2s[KC];
    __shared__ int hist_s[KC];
    int tid = threadIdx.x;

    {   // zero g_cov / g_meansum slices + scalar accumulators
        float4 z = make_float4(0.f, 0.f, 0.f, 0.f);
        float4* cz = ((float4*)g_cov) + (size_t)blockIdx.x * 1024;
        for (int i = tid; i < 1024; i += 256) cz[i] = z;
        if (tid < 8) ((float4*)g_meansum)[blockIdx.x * 8 + tid] = z;
        if (blockIdx.x == 0 && tid == 0) { g_cs_acc = 0.f; g_ms_acc = 0.f; }
    }

    if (tid < KC) hist_s[tid] = 0;
    for (int i = tid; i < KC * DD; i += 256) {
        int k = i >> 7, d = i & 127;
        cs[d * CSTR + (k >> 3) * 12 + (k & 7)] = cen[i];
    }
    if (tid < KC) {
        const float* cr = cen + tid * DD;
        float s0 = 0.f, s1 = 0.f, s2 = 0.f, s3 = 0.f;
        for (int d = 0; d < DD; d += 4) {
            s0 += cr[d] * cr[d];
            s1 += cr[d + 1] * cr[d + 1];
            s2 += cr[d + 2] * cr[d + 2];
            s3 += cr[d + 3] * cr[d + 3];
        }
        cn2s[tid] = (s0 + s1) + (s2 + s3);
    }
    __syncthreads();

    int g = blockIdx.x * 256 + tid;
    int q = g & 7;
    int pairI = g >> 3;
    int n0 = pairI * 2, n1 = n0 + 1;

    const float4* x40 = (const float4*)(x + (size_t)n0 * DD);
    const float4* x41 = (const float4*)(x + (size_t)n1 * DD);

    float acc0[8], acc1[8];
#pragma unroll
    for (int kl = 0; kl < 8; ++kl) { acc0[kl] = 0.f; acc1[kl] = 0.f; }
    float xn20 = 0.f, xn21 = 0.f;

#pragma unroll 4
    for (int ch = 0; ch < 16; ++ch) {
        float4 a = x40[ch * 2], b = x40[ch * 2 + 1];
        float4 c4 = x41[ch * 2], d4 = x41[ch * 2 + 1];
        float xa[8] = {a.x, a.y, a.z, a.w, b.x, b.y, b.z, b.w};
        float xb[8] = {c4.x, c4.y, c4.z, c4.w, d4.x, d4.y, d4.z, d4.w};
#pragma unroll
        for (int j = 0; j < 8; ++j) {
            xn20 = fmaf(xa[j], xa[j], xn20);
            xn21 = fmaf(xb[j], xb[j], xn21);
        }
        const float* cp = &cs[(ch * 8) * CSTR + q * 12];
#pragma unroll
        for (int j = 0; j < 8; ++j) {
            float4 ca = *(const float4*)(cp + j * CSTR);
            float4 cb2 = *(const float4*)(cp + j * CSTR + 4);
            acc0[0] = fmaf(xa[j], ca.x, acc0[0]);
            acc0[1] = fmaf(xa[j], ca.y, acc0[1]);
            acc0[2] = fmaf(xa[j], ca.z, acc0[2]);
            acc0[3] = fmaf(xa[j], ca.w, acc0[3]);
            acc0[4] = fmaf(xa[j], cb2.x, acc0[4]);
            acc0[5] = fmaf(xa[j], cb2.y, acc0[5]);
            acc0[6] = fmaf(xa[j], cb2.z, acc0[6]);
            acc0[7] = fmaf(xa[j], cb2.w, acc0[7]);
            acc1[0] = fmaf(xb[j], ca.x, acc1[0]);
            acc1[1] = fmaf(xb[j], ca.y, acc1[1]);
            acc1[2] = fmaf(xb[j], ca.z, acc1[2]);
            acc1[3] = fmaf(xb[j], ca.w, acc1[3]);
            acc1[4] = fmaf(xb[j], cb2.x, acc1[4]);
            acc1[5] = fmaf(xb[j], cb2.y, acc1[5]);
            acc1[6] = fmaf(xb[j], cb2.z, acc1[6]);
            acc1[7] = fmaf(xb[j], cb2.w, acc1[7]);
        }
    }

    float dist0[8], dist1[8];
    float dmin0 = 3.4e38f, dmin1 = 3.4e38f;
    int km0 = 0, km1 = 0;
#pragma unroll
    for (int kl = 0; kl < 8; ++kl) {
        float cn2 = cn2s[q * 8 + kl];
        float dv0 = fmaf(-2.f, acc0[kl], xn20 + cn2);
        float dv1 = fmaf(-2.f, acc1[kl], xn21 + cn2);
        dist0[kl] = dv0; dist1[kl] = dv1;
        if (dv0 < dmin0) { dmin0 = dv0; km0 = q * 8 + kl; }
        if (dv1 < dmin1) { dmin1 = dv1; km1 = q * 8 + kl; }
    }
#pragma unroll
    for (int m = 1; m < 8; m <<= 1) {
        float ov0 = __shfl_xor_sync(0xffffffffu, dmin0, m);
        int   oi0 = __shfl_xor_sync(0xffffffffu, km0, m);
        if (ov0 < dmin0 || (ov0 == dmin0 && oi0 < km0)) { dmin0 = ov0; km0 = oi0; }
        float ov1 = __shfl_xor_sync(0xffffffffu, dmin1, m);
        int   oi1 = __shfl_xor_sync(0xffffffffu, km1, m);
        if (ov1 < dmin1 || (ov1 == dmin1 && oi1 < km1)) { dmin1 = ov1; km1 = oi1; }
    }
    float ls0 = 0.f, ls1 = 0.f;
#pragma unroll
    for (int kl = 0; kl < 8; ++kl) {
        ls0 += __expf(-0.5f * (dist0[kl] - dmin0));
        ls1 += __expf(-0.5f * (dist1[kl] - dmin1));
    }
#pragma unroll
    for (int m = 1; m < 8; m <<= 1) {
        ls0 += __shfl_xor_sync(0xffffffffu, ls0, m);
        ls1 += __shfl_xor_sync(0xffffffffu, ls1, m);
    }
    float lg0 = logf(ls0), lg1 = logf(ls1);
    const float LM = logf(1e-8f);

    float4* o0 = (float4*)(out + (size_t)n0 * KC + q * 8);
    float4* o1 = (float4*)(out + (size_t)n1 * KC + q * 8);
#pragma unroll
    for (int v = 0; v < 2; ++v) {
        float4 r0, r1;
        r0.x = fmaxf(-0.5f * (dist0[4 * v + 0] - dmin0) - lg0, LM);
        r0.y = fmaxf(-0.5f * (dist0[4 * v + 1] - dmin0) - lg0, LM);
        r0.z = fmaxf(-0.5f * (dist0[4 * v + 2] - dmin0) - lg0, LM);
        r0.w = fmaxf(-0.5f * (dist0[4 * v + 3] - dmin0) - lg0, LM);
        r1.x = fmaxf(-0.5f * (dist1[4 * v + 0] - dmin1) - lg1, LM);
        r1.y = fmaxf(-0.5f * (dist1[4 * v + 1] - dmin1) - lg1, LM);
        r1.z = fmaxf(-0.5f * (dist1[4 * v + 2] - dmin1) - lg1, LM);
        r1.w = fmaxf(-0.5f * (dist1[4 * v + 3] - dmin1) - lg1, LM);
        o0[v] = r0; o1[v] = r1;
    }
    if (q == 0) {
        g_assign[n0] = km0;
        g_assign[n1] = km1;
        atomicAdd(&hist_s[km0], 1);
        atomicAdd(&hist_s[km1], 1);
    }
    __syncthreads();
    if (tid < KC) g_bhist[blockIdx.x * KC + tid] = hist_s[tid];
}

// ============ pass B: totals + prefix + per-chunk scatter offsets (1 block) ============
__global__ __launch_bounds__(256) void k_passB() {
    __shared__ int chunkh[NCH * KC];   // 32 KB
    __shared__ int partial[4 * KC];
    __shared__ int pre[KC + 1];
    int tid = threadIdx.x;

    for (int i = tid; i < NCH * KC; i += 256) {
        int c = i >> 6, k = i & 63;
        chunkh[i] = g_bhist[(2 * c) * KC + k] + g_bhist[(2 * c + 1) * KC + k];
    }
    __syncthreads();
    {
        int k = tid & 63, grp = tid >> 6;
        int s = 0;
        for (int c = grp * 32; c < grp * 32 + 32; ++c) s += chunkh[c * KC + k];
        partial[grp * KC + k] = s;
    }
    __syncthreads();
    if (tid == 0) {
        int acc = 0;
        for (int k = 0; k < KC; ++k) {
            pre[k] = acc;
            acc += partial[k] + partial[KC + k] + partial[2 * KC + k] + partial[3 * KC + k];
        }
        pre[KC] = acc;
    }
    __syncthreads();
    if (tid <= KC) g_off[tid] = pre[tid];
    {
        int k = tid & 63, cg = tid >> 6;
        int run = pre[k];
        for (int g2 = 0; g2 < cg; ++g2) run += partial[g2 * KC + k];
        for (int c = cg * 32; c < cg * 32 + 32; ++c) {
            g_boff2[c * KC + k] = run;
            run += chunkh[c * KC + k];
        }
    }
}

// ============ pass C: counting-sort scatter, 128 samples/block over 128 blocks ============
__global__ __launch_bounds__(128) void k_passC() {
    __shared__ int cnt[KC];
    __shared__ int base[KC];
    int t = threadIdx.x, b = blockIdx.x;
    if (t < KC) { cnt[t] = 0; base[t] = g_boff2[b * KC + t]; }
    __syncthreads();
    int n = b * 128 + t;
    int a = g_assign[n];
    int r = atomicAdd(&cnt[a], 1);
    g_sorted[base[a] + r] = n;
}

// ============ pass E: raw-moment SYRK; paired halves + red.v4 flush ============
// roles: tid 0..239 -> 120 pairs (tid>>1 = upper tile, tid&1 = interleaved half);
//        tid 240..255 -> 16 diag tiles, full batch.
__global__ __launch_bounds__(256, 2) void k_passE(const float* __restrict__ x) {
    __shared__ float xs[STG][NBE][XSP];   // ~24.8 KB
    __shared__ int offs[KC + 1];
    __shared__ int sidx[CHE2];
    int tid = threadIdx.x;

    int p0 = blockIdx.x * CHE2;
    if (p0 >= BN) return;                 // uniform per-block
    int p1 = min(p0 + CHE2, BN);

    if (tid <= KC) offs[tid] = g_off[tid];
    for (int i = tid; i < p1 - p0; i += 256) sidx[i] = g_sorted[p0 + i];

    int isDiag = (tid >= 240);
    int ti, tj, myIt, sMul, sAdd;
    if (isDiag) {
        int d = tid - 240;
        ti = d; tj = d; myIt = NBE; sMul = 1; sAdd = 0;
    } else {
        int u = tid >> 1;
        int a = 0, cnt = 15, rem = u;
        while (rem >= cnt) { rem -= cnt; a++; cnt--; }
        ti = a; tj = a + 1 + rem;
        myIt = NBE / 2; sMul = 2; sAdd = tid & 1;   // interleaved samples
    }
    int ri = ti * 8, cj = tj * 8;
    int isFlusher = isDiag || ((tid & 1) == 0);

    int myS = tid >> 4;          // sample slot 0..15 (for cp.async issue)
    int myQ = tid & 15;          // base float4 index; thread also loads myQ+16
    int sumD = tid & 127;        // dim owned for mean-sum accumulation
    int sumS0 = (tid >> 7) * (NBE / 2);   // half of the batch this thread sums
    __syncthreads();

    int k = 0;
    while (k < KC && offs[k + 1] <= p0) k++;
    for (; k < KC && offs[k] < p1; ++k) {
        int s0 = max(offs[k], p0), s1 = min(offs[k + 1], p1);
        if (s1 <= s0) continue;

        float acc[8][8];
#pragma unroll
        for (int i = 0; i < 8; ++i)
#pragma unroll
            for (int j = 0; j < 8; ++j) acc[i][j] = 0.f;
        float sumAcc = 0.f;

        int nb = (s1 - s0 + NBE - 1) / NBE;

        // prologue: issue batches 0..STG-1 (guarded), always commit
#pragma unroll
        for (int pb = 0; pb < STG; ++pb) {
            int base = s0 + pb * NBE;
            if (base < s1) {
                int pos = base + myS;
                float* d0 = &xs[pb][myS][myQ * 4];
                float* d1 = &xs[pb][myS][(myQ + 16) * 4];
                if (pos < s1) {
                    const float* src = x + (size_t)sidx[pos - p0] * DD;
                    CP_ASYNC16((unsigned int)__cvta_generic_to_shared(d0), src + myQ * 4);
                    CP_ASYNC16((unsigned int)__cvta_generic_to_shared(d1), src + (myQ + 16) * 4);
                } else {
                    *(float4*)d0 = make_float4(0.f, 0.f, 0.f, 0.f);
                    *(float4*)d1 = make_float4(0.f, 0.f, 0.f, 0.f);
                }
            }
            CP_COMMIT();
        }

        int st = 0;
        for (int bi = 0; bi < nb; ++bi) {
            CP_WAIT2();
            __syncthreads();
            for (int it = 0; it < myIt; ++it) {
                int s = sMul * it + sAdd;          // per-lane sample, uniform trip count
                const float* row = &xs[st][s][0];
                float4 a0 = *(const float4*)(row + ri);
                float4 a1 = *(const float4*)(row + ri + 4);
                float4 b0 = *(const float4*)(row + cj);
                float4 b1 = *(const float4*)(row + cj + 4);
                float rv[8] = {a0.x, a0.y, a0.z, a0.w, a1.x, a1.y, a1.z, a1.w};
                float cv[8] = {b0.x, b0.y, b0.z, b0.w, b1.x, b1.y, b1.z, b1.w};
#pragma unroll
                for (int i = 0; i < 8; ++i)
#pragma unroll
                    for (int j = 0; j < 8; ++j) acc[i][j] = fmaf(rv[i], cv[j], acc[i][j]);
            }
            // per-dim mean sums (zero-padded tails contribute 0)
#pragma unroll
            for (int s = 0; s < NBE / 2; ++s) sumAcc += xs[st][sumS0 + s][sumD];
            __syncthreads();
            // issue batch bi+STG into the just-freed stage
            {
                int base = s0 + (bi + STG) * NBE;
                if (base < s1) {
                    int pos = base + myS;
                    float* d0 = &xs[st][myS][myQ * 4];
                    float* d1 = &xs[st][myS][(myQ + 16) * 4];
                    if (pos < s1) {
                        const float* src = x + (size_t)sidx[pos - p0] * DD;
                        CP_ASYNC16((unsigned int)__cvta_generic_to_shared(d0), src + myQ * 4);
                        CP_ASYNC16((unsigned int)__cvta_generic_to_shared(d1), src + (myQ + 16) * 4);
                    } else {
                        *(float4*)d0 = make_float4(0.f, 0.f, 0.f, 0.f);
                        *(float4*)d1 = make_float4(0.f, 0.f, 0.f, 0.f);
                    }
                }
                CP_COMMIT();
            }
            if (++st == STG) st = 0;
        }

        // combine pair halves in-warp, then vector-reduce to gmem
#pragma unroll
        for (int i = 0; i < 8; ++i)
#pragma unroll
            for (int j = 0; j < 8; ++j) {
                float o = __shfl_xor_sync(0xffffffffu, acc[i][j], 1);
                if (!isDiag) acc[i][j] += o;
            }
        if (isFlusher) {
            float* cb = g_cov + (size_t)k * DD * DD;
#pragma unroll
            for (int i = 0; i < 8; ++i) {
                float* pr = &cb[(ri + i) * DD + cj];
                RED_ADD_V4(pr,     acc[i][0], acc[i][1], acc[i][2], acc[i][3]);
                RED_ADD_V4(pr + 4, acc[i][4], acc[i][5], acc[i][6], acc[i][7]);
            }
        }
        if (sumAcc != 0.f) atomicAdd(&g_meansum[k * DD + sumD], sumAcc);
    }
}

// ============ pass F1: 4 blocks/cluster slab reduction + (ticket) final scalars ============
__global__ __launch_bounds__(256) void k_passF1(const float* __restrict__ cen,
                                                float* __restrict__ out_scalars) {
    __shared__ float Trow[DD];
    __shared__ float rA[8], rB[8], rC[8];
    __shared__ int isLast;
    int b = blockIdx.x, tid = threadIdx.x;
    int k = b >> 2, r = b & 3;          // cluster, row-slab (32 rows)
    float w = (float)(g_off[k + 1] - g_off[k]);
    float inv = 1.f / (w + 1e-7f);
    float c2 = inv * (2.f - w * inv);   // exact epsilon-aware cross-term factor
    if (tid < DD) Trow[tid] = g_meansum[k * DD + tid];
    __syncthreads();

    float ds = 0.f, os = 0.f;
    const float4* cb4 = (const float4*)(g_cov + (size_t)k * DD * DD + (size_t)r * 32 * DD);
#pragma unroll
    for (int it = 0; it < 4; ++it) {
        int i4 = it * 256 + tid;        // 0..1023
        int d = r * 32 + (i4 >> 5);     // global row
        int e0 = (i4 & 31) << 2;        // col start
        float4 S = cb4[i4];
        float Td = Trow[d];
        float v[4] = {S.x, S.y, S.z, S.w};
#pragma unroll
        for (int j = 0; j < 4; ++j) {
            int e = e0 + j;
            if (e < d) continue;
            float cv = (v[j] - c2 * Td * Trow[e]) * inv;
            if (e == d) { float t2 = cv - 1.f; ds += t2 * t2; }
            else os += cv * cv;
        }
    }
    float msp = 0.f;
    if (r == 0 && tid < DD) {
        float m = Trow[tid] * inv;
        float dmc = m - cen[k * DD + tid];
        msp = w * dmc * dmc;
    }
#pragma unroll
    for (int m = 16; m > 0; m >>= 1) {
        ds  += __shfl_xor_sync(0xffffffffu, ds, m);
        os  += __shfl_xor_sync(0xffffffffu, os, m);
        msp += __shfl_xor_sync(0xffffffffu, msp, m);
    }
    if ((tid & 31) == 0) { rA[tid >> 5] = ds; rB[tid >> 5] = os; rC[tid >> 5] = msp; }
    __syncthreads();
    if (tid == 0) {
        float dsum = 0.f, osum = 0.f, msum = 0.f;
#pragma unroll
        for (int i = 0; i < 8; ++i) { dsum += rA[i]; osum += rB[i]; msum += rC[i]; }
        float bd = (float)BN * (float)DD;
        float contrib = w * dsum / bd + 2.f * w * osum / (bd * (float)(DD - 1));
        atomicAdd(&g_cs_acc, contrib);
        if (r == 0) atomicAdd(&g_ms_acc, msum);
    }
    __threadfence();
    __syncthreads();
    if (tid == 0) {
        int v = atomicAdd(&g_tickF, 1);
        isLast = (v == gridDim.x - 1) ? 1 : 0;
    }
    __syncthreads();
    if (!isLast) return;
    if (tid == 0) {
        out_scalars[0] = g_ms_acc / ((float)BN * (float)DD);
        out_scalars[1] = g_cs_acc;
        g_tickF = 0;
    }
}

extern "C" void kernel_launch(void* const* d_in, const int* in_sizes, int n_in,
                              void* d_out, int out_size) {
    const float* x = (const float*)d_in[0];
    const float* c = (const float*)d_in[1];
    float* out = (float*)d_out;

    k_passA<<<NBLK_A, 256>>>(x, c, out);
    k_passB<<<1, 256>>>();
    k_passC<<<NCH, 128>>>();
    k_passE<<<NBLK_E, 256>>>(x);   // launch index 3 -> profiled next round
    k_passF1<<<KC * 4, 256>>>(c, out + (out_size - 2));
}

// round 15
// speedup vs baseline: 2.8756x; 1.0874x over previous
#include <cuda_runtime.h>
#include <cstdint>
#include <math.h>

#define BN 16384
#define KC 64
#define DD 128
#define NBLK_A 256
#define CSTR 92   // cs row stride in words (group q at q*12, 8 floats per group)

#define NBE 16         // samples per passE batch
#define STG 3          // cp.async pipeline stages
#define NBLK_E 296
#define CHE2 56
#define XSP 132        // padded row stride (floats) for xs
#define NCH 128        // passC chunks (128 samples each)

__device__ int   g_assign[BN];
__device__ int   g_bhist[NBLK_A * KC];
__device__ int   g_boff2[NCH * KC];
__device__ int   g_off[KC + 1];
__device__ int   g_sorted[BN];
__device__ float g_meansum[KC * DD];
__device__ float g_cs_acc, g_ms_acc;
__device__ float g_cov[KC * DD * DD];
__device__ int   g_tickF;

#define CP_ASYNC16(dst, src) \
    asm volatile("cp.async.cg.shared.global [%0], [%1], 16;" :: "r"(dst), "l"(src))
#define CP_COMMIT() asm volatile("cp.async.commit_group;")
#define CP_WAIT2()  asm volatile("cp.async.wait_group 2;")
#define RED_ADD_V4(ptr, a, b, c, d) \
    asm volatile("red.global.add.v4.f32 [%0], {%1, %2, %3, %4};" \
                 :: "l"(ptr), "f"(a), "f"(b), "f"(c), "f"(d) : "memory")

// ============ pass A: zero scratch + dist/log_resp/argmin + per-block hist ============
// thread: 4 consecutive samples x 8 clusters (octant q = g&7), 128 dims.
// 256 blocks x 128 threads; each center LDS.128 pair feeds 32 FMA.
__global__ __launch_bounds__(128) void k_passA(const float* __restrict__ x,
                                               const float* __restrict__ cen,
                                               float* __restrict__ out) {
    __shared__ float cs[DD * CSTR];
    __shared__ float cn2s[KC];
    __shared__ int hist_s[KC];
    int tid = threadIdx.x;

    {   // zero g_cov / g_meansum slices + scalar accumulators
        float4 z = make_float4(0.f, 0.f, 0.f, 0.f);
        float4* cz = ((float4*)g_cov) + (size_t)blockIdx.x * 1024;
        for (int i = tid; i < 1024; i += 128) cz[i] = z;
        if (tid < 8) ((float4*)g_meansum)[blockIdx.x * 8 + tid] = z;
        if (blockIdx.x == 0 && tid == 0) { g_cs_acc = 0.f; g_ms_acc = 0.f; }
    }

    if (tid < KC) hist_s[tid] = 0;
    for (int i = tid; i < KC * DD; i += 128) {
        int k = i >> 7, d = i & 127;
        cs[d * CSTR + (k >> 3) * 12 + (k & 7)] = cen[i];
    }
    if (tid < KC) {
        const float* cr = cen + tid * DD;
        float s0 = 0.f, s1 = 0.f, s2 = 0.f, s3 = 0.f;
        for (int d = 0; d < DD; d += 4) {
            s0 += cr[d] * cr[d];
            s1 += cr[d + 1] * cr[d + 1];
            s2 += cr[d + 2] * cr[d + 2];
            s3 += cr[d + 3] * cr[d + 3];
        }
        cn2s[tid] = (s0 + s1) + (s2 + s3);
    }
    __syncthreads();

    int g = blockIdx.x * 128 + tid;
    int q = g & 7;                 // cluster octant
    int grp = g >> 3;              // 0..4095
    int nb0 = grp * 4;             // first of 4 samples

    const float4* xr[4];
#pragma unroll
    for (int s = 0; s < 4; ++s) xr[s] = (const float4*)(x + (size_t)(nb0 + s) * DD);

    float acc[4][8];
#pragma unroll
    for (int s = 0; s < 4; ++s)
#pragma unroll
        for (int kl = 0; kl < 8; ++kl) acc[s][kl] = 0.f;
    float xn[4] = {0.f, 0.f, 0.f, 0.f};

#pragma unroll 2
    for (int ch = 0; ch < 16; ++ch) {
        float xa[4][8];
#pragma unroll
        for (int s = 0; s < 4; ++s) {
            float4 a = xr[s][ch * 2], b = xr[s][ch * 2 + 1];
            xa[s][0] = a.x; xa[s][1] = a.y; xa[s][2] = a.z; xa[s][3] = a.w;
            xa[s][4] = b.x; xa[s][5] = b.y; xa[s][6] = b.z; xa[s][7] = b.w;
#pragma unroll
            for (int j = 0; j < 8; ++j) xn[s] = fmaf(xa[s][j], xa[s][j], xn[s]);
        }
        const float* cp = &cs[(ch * 8) * CSTR + q * 12];
#pragma unroll
        for (int j = 0; j < 8; ++j) {
            float4 ca = *(const float4*)(cp + j * CSTR);
            float4 cb2 = *(const float4*)(cp + j * CSTR + 4);
            float cv[8] = {ca.x, ca.y, ca.z, ca.w, cb2.x, cb2.y, cb2.z, cb2.w};
#pragma unroll
            for (int s = 0; s < 4; ++s)
#pragma unroll
                for (int kl = 0; kl < 8; ++kl)
                    acc[s][kl] = fmaf(xa[s][j], cv[kl], acc[s][kl]);
        }
    }

    // dist, argmin, softmax per sample (in-place into acc)
    float dmin[4];
    int km[4];
#pragma unroll
    for (int s = 0; s < 4; ++s) {
        dmin[s] = 3.4e38f; km[s] = 0;
#pragma unroll
        for (int kl = 0; kl < 8; ++kl) {
            float dv = fmaf(-2.f, acc[s][kl], xn[s] + cn2s[q * 8 + kl]);
            acc[s][kl] = dv;
            if (dv < dmin[s]) { dmin[s] = dv; km[s] = q * 8 + kl; }
        }
    }
#pragma unroll
    for (int m = 1; m < 8; m <<= 1) {
#pragma unroll
        for (int s = 0; s < 4; ++s) {
            float ov = __shfl_xor_sync(0xffffffffu, dmin[s], m);
            int   oi = __shfl_xor_sync(0xffffffffu, km[s], m);
            if (ov < dmin[s] || (ov == dmin[s] && oi < km[s])) { dmin[s] = ov; km[s] = oi; }
        }
    }
    float ls[4];
#pragma unroll
    for (int s = 0; s < 4; ++s) {
        float t = 0.f;
#pragma unroll
        for (int kl = 0; kl < 8; ++kl) t += __expf(-0.5f * (acc[s][kl] - dmin[s]));
        ls[s] = t;
    }
#pragma unroll
    for (int m = 1; m < 8; m <<= 1) {
#pragma unroll
        for (int s = 0; s < 4; ++s) ls[s] += __shfl_xor_sync(0xffffffffu, ls[s], m);
    }
    const float LM = logf(1e-8f);
#pragma unroll
    for (int s = 0; s < 4; ++s) {
        float lg = logf(ls[s]);
        float4* o = (float4*)(out + (size_t)(nb0 + s) * KC + q * 8);
        float4 r0, r1;
        r0.x = fmaxf(-0.5f * (acc[s][0] - dmin[s]) - lg, LM);
        r0.y = fmaxf(-0.5f * (acc[s][1] - dmin[s]) - lg, LM);
        r0.z = fmaxf(-0.5f * (acc[s][2] - dmin[s]) - lg, LM);
        r0.w = fmaxf(-0.5f * (acc[s][3] - dmin[s]) - lg, LM);
        r1.x = fmaxf(-0.5f * (acc[s][4] - dmin[s]) - lg, LM);
        r1.y = fmaxf(-0.5f * (acc[s][5] - dmin[s]) - lg, LM);
        r1.z = fmaxf(-0.5f * (acc[s][6] - dmin[s]) - lg, LM);
        r1.w = fmaxf(-0.5f * (acc[s][7] - dmin[s]) - lg, LM);
        o[0] = r0; o[1] = r1;
    }
    if (q == 0) {
#pragma unroll
        for (int s = 0; s < 4; ++s) {
            g_assign[nb0 + s] = km[s];
            atomicAdd(&hist_s[km[s]], 1);
        }
    }
    __syncthreads();
    if (tid < KC) g_bhist[blockIdx.x * KC + tid] = hist_s[tid];
}

// ============ pass B: totals + prefix + per-chunk scatter offsets (1 block) ============
__global__ __launch_bounds__(256) void k_passB() {
    __shared__ int chunkh[NCH * KC];   // 32 KB
    __shared__ int partial[4 * KC];
    __shared__ int pre[KC + 1];
    int tid = threadIdx.x;

    for (int i = tid; i < NCH * KC; i += 256) {
        int c = i >> 6, k = i & 63;
        chunkh[i] = g_bhist[(2 * c) * KC + k] + g_bhist[(2 * c + 1) * KC + k];
    }
    __syncthreads();
    {
        int k = tid & 63, grp = tid >> 6;
        int s = 0;
        for (int c = grp * 32; c < grp * 32 + 32; ++c) s += chunkh[c * KC + k];
        partial[grp * KC + k] = s;
    }
    __syncthreads();
    if (tid == 0) {
        int acc = 0;
        for (int k = 0; k < KC; ++k) {
            pre[k] = acc;
            acc += partial[k] + partial[KC + k] + partial[2 * KC + k] + partial[3 * KC + k];
        }
        pre[KC] = acc;
    }
    __syncthreads();
    if (tid <= KC) g_off[tid] = pre[tid];
    {
        int k = tid & 63, cg = tid >> 6;
        int run = pre[k];
        for (int g2 = 0; g2 < cg; ++g2) run += partial[g2 * KC + k];
        for (int c = cg * 32; c < cg * 32 + 32; ++c) {
            g_boff2[c * KC + k] = run;
            run += chunkh[c * KC + k];
        }
    }
}

// ============ pass C: counting-sort scatter, 128 samples/block over 128 blocks ============
__global__ __launch_bounds__(128) void k_passC() {
    __shared__ int cnt[KC];
    __shared__ int base[KC];
    int t = threadIdx.x, b = blockIdx.x;
    if (t < KC) { cnt[t] = 0; base[t] = g_boff2[b * KC + t]; }
    __syncthreads();
    int n = b * 128 + t;
    int a = g_assign[n];
    int r = atomicAdd(&cnt[a], 1);
    g_sorted[base[a] + r] = n;
}

// ============ pass E: raw-moment SYRK; paired halves + red.v4 flush ============
__global__ __launch_bounds__(256, 2) void k_passE(const float* __restrict__ x) {
    __shared__ float xs[STG][NBE][XSP];   // ~24.8 KB
    __shared__ int offs[KC + 1];
    __shared__ int sidx[CHE2];
    int tid = threadIdx.x;

    int p0 = blockIdx.x * CHE2;
    if (p0 >= BN) return;                 // uniform per-block
    int p1 = min(p0 + CHE2, BN);

    if (tid <= KC) offs[tid] = g_off[tid];
    for (int i = tid; i < p1 - p0; i += 256) sidx[i] = g_sorted[p0 + i];

    int isDiag = (tid >= 240);
    int ti, tj, myIt, sMul, sAdd;
    if (isDiag) {
        int d = tid - 240;
        ti = d; tj = d; myIt = NBE; sMul = 1; sAdd = 0;
    } else {
        int u = tid >> 1;
        int a = 0, cnt = 15, rem = u;
        while (rem >= cnt) { rem -= cnt; a++; cnt--; }
        ti = a; tj = a + 1 + rem;
        myIt = NBE / 2; sMul = 2; sAdd = tid & 1;   // interleaved samples
    }
    int ri = ti * 8, cj = tj * 8;
    int isFlusher = isDiag || ((tid & 1) == 0);

    int myS = tid >> 4;          // sample slot 0..15 (for cp.async issue)
    int myQ = tid & 15;          // base float4 index; thread also loads myQ+16
    int sumD = tid & 127;        // dim owned for mean-sum accumulation
    int sumS0 = (tid >> 7) * (NBE / 2);   // half of the batch this thread sums
    __syncthreads();

    int k = 0;
    while (k < KC && offs[k + 1] <= p0) k++;
    for (; k < KC && offs[k] < p1; ++k) {
        int s0 = max(offs[k], p0), s1 = min(offs[k + 1], p1);
        if (s1 <= s0) continue;

        float acc[8][8];
#pragma unroll
        for (int i = 0; i < 8; ++i)
#pragma unroll
            for (int j = 0; j < 8; ++j) acc[i][j] = 0.f;
        float sumAcc = 0.f;

        int nb = (s1 - s0 + NBE - 1) / NBE;

        // prologue: issue batches 0..STG-1 (guarded), always commit
#pragma unroll
        for (int pb = 0; pb < STG; ++pb) {
            int base = s0 + pb * NBE;
            if (base < s1) {
                int pos = base + myS;
                float* d0 = &xs[pb][myS][myQ * 4];
                float* d1 = &xs[pb][myS][(myQ + 16) * 4];
                if (pos < s1) {
                    const float* src = x + (size_t)sidx[pos - p0] * DD;
                    CP_ASYNC16((unsigned int)__cvta_generic_to_shared(d0), src + myQ * 4);
                    CP_ASYNC16((unsigned int)__cvta_generic_to_shared(d1), src + (myQ + 16) * 4);
                } else {
                    *(float4*)d0 = make_float4(0.f, 0.f, 0.f, 0.f);
                    *(float4*)d1 = make_float4(0.f, 0.f, 0.f, 0.f);
                }
            }
            CP_COMMIT();
        }

        int st = 0;
        for (int bi = 0; bi < nb; ++bi) {
            CP_WAIT2();
            __syncthreads();
            for (int it = 0; it < myIt; ++it) {
                int s = sMul * it + sAdd;          // per-lane sample, uniform trip count
                const float* row = &xs[st][s][0];
                float4 a0 = *(const float4*)(row + ri);
                float4 a1 = *(const float4*)(row + ri + 4);
                float4 b0 = *(const float4*)(row + cj);
                float4 b1 = *(const float4*)(row + cj + 4);
                float rv[8] = {a0.x, a0.y, a0.z, a0.w, a1.x, a1.y, a1.z, a1.w};
                float cv[8] = {b0.x, b0.y, b0.z, b0.w, b1.x, b1.y, b1.z, b1.w};
#pragma unroll
                for (int i = 0; i < 8; ++i)
#pragma unroll
                    for (int j = 0; j < 8; ++j) acc[i][j] = fmaf(rv[i], cv[j], acc[i][j]);
            }
            // per-dim mean sums (zero-padded tails contribute 0)
#pragma unroll
            for (int s = 0; s < NBE / 2; ++s) sumAcc += xs[st][sumS0 + s][sumD];
            __syncthreads();
            // issue batch bi+STG into the just-freed stage
            {
                int base = s0 + (bi + STG) * NBE;
                if (base < s1) {
                    int pos = base + myS;
                    float* d0 = &xs[st][myS][myQ * 4];
                    float* d1 = &xs[st][myS][(myQ + 16) * 4];
                    if (pos < s1) {
                        const float* src = x + (size_t)sidx[pos - p0] * DD;
                        CP_ASYNC16((unsigned int)__cvta_generic_to_shared(d0), src + myQ * 4);
                        CP_ASYNC16((unsigned int)__cvta_generic_to_shared(d1), src + (myQ + 16) * 4);
                    } else {
                        *(float4*)d0 = make_float4(0.f, 0.f, 0.f, 0.f);
                        *(float4*)d1 = make_float4(0.f, 0.f, 0.f, 0.f);
                    }
                }
                CP_COMMIT();
            }
            if (++st == STG) st = 0;
        }

        // combine pair halves in-warp, then vector-reduce to gmem
#pragma unroll
        for (int i = 0; i < 8; ++i)
#pragma unroll
            for (int j = 0; j < 8; ++j) {
                float o = __shfl_xor_sync(0xffffffffu, acc[i][j], 1);
                if (!isDiag) acc[i][j] += o;
            }
        if (isFlusher) {
            float* cb = g_cov + (size_t)k * DD * DD;
#pragma unroll
            for (int i = 0; i < 8; ++i) {
                float* pr = &cb[(ri + i) * DD + cj];
                RED_ADD_V4(pr,     acc[i][0], acc[i][1], acc[i][2], acc[i][3]);
                RED_ADD_V4(pr + 4, acc[i][4], acc[i][5], acc[i][6], acc[i][7]);
            }
        }
        if (sumAcc != 0.f) atomicAdd(&g_meansum[k * DD + sumD], sumAcc);
    }
}

// ============ pass F1: 4 blocks/cluster slab reduction + (ticket) final scalars ============
__global__ __launch_bounds__(256) void k_passF1(const float* __restrict__ cen,
                                                float* __restrict__ out_scalars) {
    __shared__ float Trow[DD];
    __shared__ float rA[8], rB[8], rC[8];
    __shared__ int isLast;
    int b = blockIdx.x, tid = threadIdx.x;
    int k = b >> 2, r = b & 3;          // cluster, row-slab (32 rows)
    float w = (float)(g_off[k + 1] - g_off[k]);
    float inv = 1.f / (w + 1e-7f);
    float c2 = inv * (2.f - w * inv);   // exact epsilon-aware cross-term factor
    if (tid < DD) Trow[tid] = g_meansum[k * DD + tid];
    __syncthreads();

    float ds = 0.f, os = 0.f;
    const float4* cb4 = (const float4*)(g_cov + (size_t)k * DD * DD + (size_t)r * 32 * DD);
#pragma unroll
    for (int it = 0; it < 4; ++it) {
        int i4 = it * 256 + tid;        // 0..1023
        int d = r * 32 + (i4 >> 5);     // global row
        int e0 = (i4 & 31) << 2;        // col start
        float4 S = cb4[i4];
        float Td = Trow[d];
        float v[4] = {S.x, S.y, S.z, S.w};
#pragma unroll
        for (int j = 0; j < 4; ++j) {
            int e = e0 + j;
            if (e < d) continue;
            float cv = (v[j] - c2 * Td * Trow[e]) * inv;
            if (e == d) { float t2 = cv - 1.f; ds += t2 * t2; }
            else os += cv * cv;
        }
    }
    float msp = 0.f;
    if (r == 0 && tid < DD) {
        float m = Trow[tid] * inv;
        float dmc = m - cen[k * DD + tid];
        msp = w * dmc * dmc;
    }
#pragma unroll
    for (int m = 16; m > 0; m >>= 1) {
        ds  += __shfl_xor_sync(0xffffffffu, ds, m);
        os  += __shfl_xor_sync(0xffffffffu, os, m);
        msp += __shfl_xor_sync(0xffffffffu, msp, m);
    }
    if ((tid & 31) == 0) { rA[tid >> 5] = ds; rB[tid >> 5] = os; rC[tid >> 5] = msp; }
    __syncthreads();
    if (tid == 0) {
        float dsum = 0.f, osum = 0.f, msum = 0.f;
#pragma unroll
        for (int i = 0; i < 8; ++i) { dsum += rA[i]; osum += rB[i]; msum += rC[i]; }
        float bd = (float)BN * (float)DD;
        float contrib = w * dsum / bd + 2.f * w * osum / (bd * (float)(DD - 1));
        atomicAdd(&g_cs_acc, contrib);
        if (r == 0) atomicAdd(&g_ms_acc, msum);
    }
    __threadfence();
    __syncthreads();
    if (tid == 0) {
        int v = atomicAdd(&g_tickF, 1);
        isLast = (v == gridDim.x - 1) ? 1 : 0;
    }
    __syncthreads();
    if (!isLast) return;
    if (tid == 0) {
        out_scalars[0] = g_ms_acc / ((float)BN * (float)DD);
        out_scalars[1] = g_cs_acc;
        g_tickF = 0;
    }
}

extern "C" void kernel_launch(void* const* d_in, const int* in_sizes, int n_in,
                              void* d_out, int out_size) {
    const float* x = (const float*)d_in[0];
    const float* c = (const float*)d_in[1];
    float* out = (float*)d_out;

    k_passA<<<NBLK_A, 128>>>(x, c, out);
    k_passB<<<1, 256>>>();
    k_passC<<<NCH, 128>>>();
    k_passE<<<NBLK_E, 256>>>(x);   // launch index 3 -> profiled next round
    k_passF1<<<KC * 4, 256>>>(c, out + (out_size - 2));
}

// round 16
// speedup vs baseline: 3.0262x; 1.0524x over previous
#include <cuda_runtime.h>
#include <cstdint>
#include <math.h>

#define BN 16384
#define KC 64
#define DD 128
#define NBLK_A 256
#define CSTR 92   // cs row stride in words (group q at q*12, 8 floats per group)

#define NBLK_E 296
#define CHE2 56
#define XSP 132        // padded row stride (floats) for xs
#define NCH 128        // passC chunks (128 samples each)

__device__ int   g_assign[BN];
__device__ int   g_bhist[NBLK_A * KC];
__device__ int   g_boff2[NCH * KC];
__device__ int   g_off[KC + 1];
__device__ int   g_sorted[BN];
__device__ float g_meansum[KC * DD];
__device__ float g_cs_acc, g_ms_acc;
__device__ float g_cov[KC * DD * DD];
__device__ int   g_tickF;

#define CP_ASYNC16(dst, src) \
    asm volatile("cp.async.cg.shared.global [%0], [%1], 16;" :: "r"(dst), "l"(src))
#define CP_COMMIT() asm volatile("cp.async.commit_group;")
#define CP_WAIT0()  asm volatile("cp.async.wait_group 0;")
#define RED_ADD_V4(ptr, a, b, c, d) \
    asm volatile("red.global.add.v4.f32 [%0], {%1, %2, %3, %4};" \
                 :: "l"(ptr), "f"(a), "f"(b), "f"(c), "f"(d) : "memory")

// ============ pass A: zero scratch + dist/log_resp/argmin + per-block hist ============
// thread: 4 consecutive samples x 8 clusters (octant q = g&7), 128 dims.
__global__ __launch_bounds__(128) void k_passA(const float* __restrict__ x,
                                               const float* __restrict__ cen,
                                               float* __restrict__ out) {
    __shared__ float cs[DD * CSTR];
    __shared__ float cn2s[KC];
    __shared__ int hist_s[KC];
    int tid = threadIdx.x;

    {   // zero g_cov / g_meansum slices + scalar accumulators
        float4 z = make_float4(0.f, 0.f, 0.f, 0.f);
        float4* cz = ((float4*)g_cov) + (size_t)blockIdx.x * 1024;
        for (int i = tid; i < 1024; i += 128) cz[i] = z;
        if (tid < 8) ((float4*)g_meansum)[blockIdx.x * 8 + tid] = z;
        if (blockIdx.x == 0 && tid == 0) { g_cs_acc = 0.f; g_ms_acc = 0.f; }
    }

    if (tid < KC) hist_s[tid] = 0;
    for (int i = tid; i < KC * DD; i += 128) {
        int k = i >> 7, d = i & 127;
        cs[d * CSTR + (k >> 3) * 12 + (k & 7)] = cen[i];
    }
    if (tid < KC) {
        const float* cr = cen + tid * DD;
        float s0 = 0.f, s1 = 0.f, s2 = 0.f, s3 = 0.f;
        for (int d = 0; d < DD; d += 4) {
            s0 += cr[d] * cr[d];
            s1 += cr[d + 1] * cr[d + 1];
            s2 += cr[d + 2] * cr[d + 2];
            s3 += cr[d + 3] * cr[d + 3];
        }
        cn2s[tid] = (s0 + s1) + (s2 + s3);
    }
    __syncthreads();

    int g = blockIdx.x * 128 + tid;
    int q = g & 7;                 // cluster octant
    int grp = g >> 3;              // 0..4095
    int nb0 = grp * 4;             // first of 4 samples

    const float4* xr[4];
#pragma unroll
    for (int s = 0; s < 4; ++s) xr[s] = (const float4*)(x + (size_t)(nb0 + s) * DD);

    float acc[4][8];
#pragma unroll
    for (int s = 0; s < 4; ++s)
#pragma unroll
        for (int kl = 0; kl < 8; ++kl) acc[s][kl] = 0.f;
    float xn[4] = {0.f, 0.f, 0.f, 0.f};

#pragma unroll 2
    for (int ch = 0; ch < 16; ++ch) {
        float xa[4][8];
#pragma unroll
        for (int s = 0; s < 4; ++s) {
            float4 a = xr[s][ch * 2], b = xr[s][ch * 2 + 1];
            xa[s][0] = a.x; xa[s][1] = a.y; xa[s][2] = a.z; xa[s][3] = a.w;
            xa[s][4] = b.x; xa[s][5] = b.y; xa[s][6] = b.z; xa[s][7] = b.w;
#pragma unroll
            for (int j = 0; j < 8; ++j) xn[s] = fmaf(xa[s][j], xa[s][j], xn[s]);
        }
        const float* cp = &cs[(ch * 8) * CSTR + q * 12];
#pragma unroll
        for (int j = 0; j < 8; ++j) {
            float4 ca = *(const float4*)(cp + j * CSTR);
            float4 cb2 = *(const float4*)(cp + j * CSTR + 4);
            float cv[8] = {ca.x, ca.y, ca.z, ca.w, cb2.x, cb2.y, cb2.z, cb2.w};
#pragma unroll
            for (int s = 0; s < 4; ++s)
#pragma unroll
                for (int kl = 0; kl < 8; ++kl)
                    acc[s][kl] = fmaf(xa[s][j], cv[kl], acc[s][kl]);
        }
    }

    float dmin[4];
    int km[4];
#pragma unroll
    for (int s = 0; s < 4; ++s) {
        dmin[s] = 3.4e38f; km[s] = 0;
#pragma unroll
        for (int kl = 0; kl < 8; ++kl) {
            float dv = fmaf(-2.f, acc[s][kl], xn[s] + cn2s[q * 8 + kl]);
            acc[s][kl] = dv;
            if (dv < dmin[s]) { dmin[s] = dv; km[s] = q * 8 + kl; }
        }
    }
#pragma unroll
    for (int m = 1; m < 8; m <<= 1) {
#pragma unroll
        for (int s = 0; s < 4; ++s) {
            float ov = __shfl_xor_sync(0xffffffffu, dmin[s], m);
            int   oi = __shfl_xor_sync(0xffffffffu, km[s], m);
            if (ov < dmin[s] || (ov == dmin[s] && oi < km[s])) { dmin[s] = ov; km[s] = oi; }
        }
    }
    float ls[4];
#pragma unroll
    for (int s = 0; s < 4; ++s) {
        float t = 0.f;
#pragma unroll
        for (int kl = 0; kl < 8; ++kl) t += __expf(-0.5f * (acc[s][kl] - dmin[s]));
        ls[s] = t;
    }
#pragma unroll
    for (int m = 1; m < 8; m <<= 1) {
#pragma unroll
        for (int s = 0; s < 4; ++s) ls[s] += __shfl_xor_sync(0xffffffffu, ls[s], m);
    }
    const float LM = logf(1e-8f);
#pragma unroll
    for (int s = 0; s < 4; ++s) {
        float lg = logf(ls[s]);
        float4* o = (float4*)(out + (size_t)(nb0 + s) * KC + q * 8);
        float4 r0, r1;
        r0.x = fmaxf(-0.5f * (acc[s][0] - dmin[s]) - lg, LM);
        r0.y = fmaxf(-0.5f * (acc[s][1] - dmin[s]) - lg, LM);
        r0.z = fmaxf(-0.5f * (acc[s][2] - dmin[s]) - lg, LM);
        r0.w = fmaxf(-0.5f * (acc[s][3] - dmin[s]) - lg, LM);
        r1.x = fmaxf(-0.5f * (acc[s][4] - dmin[s]) - lg, LM);
        r1.y = fmaxf(-0.5f * (acc[s][5] - dmin[s]) - lg, LM);
        r1.z = fmaxf(-0.5f * (acc[s][6] - dmin[s]) - lg, LM);
        r1.w = fmaxf(-0.5f * (acc[s][7] - dmin[s]) - lg, LM);
        o[0] = r0; o[1] = r1;
    }
    if (q == 0) {
#pragma unroll
        for (int s = 0; s < 4; ++s) {
            g_assign[nb0 + s] = km[s];
            atomicAdd(&hist_s[km[s]], 1);
        }
    }
    __syncthreads();
    if (tid < KC) g_bhist[blockIdx.x * KC + tid] = hist_s[tid];
}

// ============ pass B: totals + prefix + per-chunk scatter offsets (1 block) ============
__global__ __launch_bounds__(256) void k_passB() {
    __shared__ int chunkh[NCH * KC];   // 32 KB
    __shared__ int partial[4 * KC];
    __shared__ int pre[KC + 1];
    int tid = threadIdx.x;

    for (int i = tid; i < NCH * KC; i += 256) {
        int c = i >> 6, k = i & 63;
        chunkh[i] = g_bhist[(2 * c) * KC + k] + g_bhist[(2 * c + 1) * KC + k];
    }
    __syncthreads();
    {
        int k = tid & 63, grp = tid >> 6;
        int s = 0;
        for (int c = grp * 32; c < grp * 32 + 32; ++c) s += chunkh[c * KC + k];
        partial[grp * KC + k] = s;
    }
    __syncthreads();
    if (tid == 0) {
        int acc = 0;
        for (int k = 0; k < KC; ++k) {
            pre[k] = acc;
            acc += partial[k] + partial[KC + k] + partial[2 * KC + k] + partial[3 * KC + k];
        }
        pre[KC] = acc;
    }
    __syncthreads();
    if (tid <= KC) g_off[tid] = pre[tid];
    {
        int k = tid & 63, cg = tid >> 6;
        int run = pre[k];
        for (int g2 = 0; g2 < cg; ++g2) run += partial[g2 * KC + k];
        for (int c = cg * 32; c < cg * 32 + 32; ++c) {
            g_boff2[c * KC + k] = run;
            run += chunkh[c * KC + k];
        }
    }
}

// ============ pass C: counting-sort scatter, 128 samples/block over 128 blocks ============
__global__ __launch_bounds__(128) void k_passC() {
    __shared__ int cnt[KC];
    __shared__ int base[KC];
    int t = threadIdx.x, b = blockIdx.x;
    if (t < KC) { cnt[t] = 0; base[t] = g_boff2[b * KC + t]; }
    __syncthreads();
    int n = b * 128 + t;
    int a = g_assign[n];
    int r = atomicAdd(&cnt[a], 1);
    g_sorted[base[a] + r] = n;
}

// ============ pass E: whole-chunk-resident SYRK; barrier-free segment loop ============
// roles: tid 0..239 -> 120 pairs (tid>>1 = upper tile, tid&1 = interleaved half);
//        tid 240..255 -> 16 diag tiles, all rows.
__global__ __launch_bounds__(256, 2) void k_passE(const float* __restrict__ x) {
    __shared__ float xs[CHE2][XSP];       // ~29.6 KB
    __shared__ int offs[KC + 1];
    __shared__ int sidx[CHE2];
    int tid = threadIdx.x;

    int p0 = blockIdx.x * CHE2;
    if (p0 >= BN) return;                 // uniform per-block
    int p1 = min(p0 + CHE2, BN);
    int nrow = p1 - p0;

    if (tid <= KC) offs[tid] = g_off[tid];
    for (int i = tid; i < nrow; i += 256) sidx[i] = g_sorted[p0 + i];
    __syncthreads();

    // whole-chunk cp.async load: nrow*32 float4, 256 threads
    for (int idx = tid; idx < nrow * 32; idx += 256) {
        int r = idx >> 5, quad = idx & 31;
        float* dgen = &xs[r][quad * 4];
        const float* src = x + (size_t)sidx[r] * DD + quad * 4;
        CP_ASYNC16((unsigned int)__cvta_generic_to_shared(dgen), src);
    }
    CP_COMMIT();

    int isDiag = (tid >= 240);
    int ti, tj, sAdd, sStep;
    if (isDiag) {
        int d = tid - 240;
        ti = d; tj = d; sAdd = 0; sStep = 1;
    } else {
        int u = tid >> 1;
        int a = 0, cnt = 15, rem = u;
        while (rem >= cnt) { rem -= cnt; a++; cnt--; }
        ti = a; tj = a + 1 + rem;
        sAdd = tid & 1; sStep = 2;       // interleaved rows
    }
    int ri = ti * 8, cj = tj * 8;
    int isFlusher = isDiag || ((tid & 1) == 0);
    int sumD = tid & 127;                // dim owned for mean-sum accumulation
    int sumH = tid >> 7;                 // row-parity half for mean sums

    CP_WAIT0();
    __syncthreads();

    int k = 0;
    while (k < KC && offs[k + 1] <= p0) k++;
    for (; k < KC && offs[k] < p1; ++k) {
        int s0 = max(offs[k], p0) - p0, s1 = min(offs[k + 1], p1) - p0;
        if (s1 <= s0) continue;

        float acc[8][8];
#pragma unroll
        for (int i = 0; i < 8; ++i)
#pragma unroll
            for (int j = 0; j < 8; ++j) acc[i][j] = 0.f;

        for (int r = s0 + sAdd; r < s1; r += sStep) {
            const float* row = &xs[r][0];
            float4 a0 = *(const float4*)(row + ri);
            float4 a1 = *(const float4*)(row + ri + 4);
            float4 b0 = *(const float4*)(row + cj);
            float4 b1 = *(const float4*)(row + cj + 4);
            float rv[8] = {a0.x, a0.y, a0.z, a0.w, a1.x, a1.y, a1.z, a1.w};
            float cv[8] = {b0.x, b0.y, b0.z, b0.w, b1.x, b1.y, b1.z, b1.w};
#pragma unroll
            for (int i = 0; i < 8; ++i)
#pragma unroll
                for (int j = 0; j < 8; ++j) acc[i][j] = fmaf(rv[i], cv[j], acc[i][j]);
        }

        // per-dim mean sums over this segment
        float sumAcc = 0.f;
        for (int r = s0 + sumH; r < s1; r += 2) sumAcc += xs[r][sumD];

        // combine pair halves in-warp, then vector-reduce to gmem
#pragma unroll
        for (int i = 0; i < 8; ++i)
#pragma unroll
            for (int j = 0; j < 8; ++j) {
                float o = __shfl_xor_sync(0xffffffffu, acc[i][j], 1);
                if (!isDiag) acc[i][j] += o;
            }
        if (isFlusher) {
            float* cb = g_cov + (size_t)k * DD * DD;
#pragma unroll
            for (int i = 0; i < 8; ++i) {
                float* pr = &cb[(ri + i) * DD + cj];
                RED_ADD_V4(pr,     acc[i][0], acc[i][1], acc[i][2], acc[i][3]);
                RED_ADD_V4(pr + 4, acc[i][4], acc[i][5], acc[i][6], acc[i][7]);
            }
        }
        if (sumAcc != 0.f) atomicAdd(&g_meansum[k * DD + sumD], sumAcc);
    }
}

// ============ pass F1: 8 blocks/cluster slab reduction + (ticket) final scalars ============
__global__ __launch_bounds__(256) void k_passF1(const float* __restrict__ cen,
                                                float* __restrict__ out_scalars) {
    __shared__ float Trow[DD];
    __shared__ float rA[8], rB[8], rC[8];
    __shared__ int isLast;
    int b = blockIdx.x, tid = threadIdx.x;
    int k = b >> 3, r = b & 7;          // cluster, row-slab (16 rows)
    float w = (float)(g_off[k + 1] - g_off[k]);
    float inv = 1.f / (w + 1e-7f);
    float c2 = inv * (2.f - w * inv);   // exact epsilon-aware cross-term factor
    if (tid < DD) Trow[tid] = g_meansum[k * DD + tid];
    __syncthreads();

    float ds = 0.f, os = 0.f;
    const float4* cb4 = (const float4*)(g_cov + (size_t)k * DD * DD + (size_t)r * 16 * DD);
#pragma unroll
    for (int it = 0; it < 2; ++it) {
        int i4 = it * 256 + tid;        // 0..511
        int d = r * 16 + (i4 >> 5);     // global row
        int e0 = (i4 & 31) << 2;        // col start
        float4 S = cb4[i4];
        float Td = Trow[d];
        float v[4] = {S.x, S.y, S.z, S.w};
#pragma unroll
        for (int j = 0; j < 4; ++j) {
            int e = e0 + j;
            if (e < d) continue;
            float cv = (v[j] - c2 * Td * Trow[e]) * inv;
            if (e == d) { float t2 = cv - 1.f; ds += t2 * t2; }
            else os += cv * cv;
        }
    }
    float msp = 0.f;
    if (r == 0 && tid < DD) {
        float m = Trow[tid] * inv;
        float dmc = m - cen[k * DD + tid];
        msp = w * dmc * dmc;
    }
#pragma unroll
    for (int m = 16; m > 0; m >>= 1) {
        ds  += __shfl_xor_sync(0xffffffffu, ds, m);
        os  += __shfl_xor_sync(0xffffffffu, os, m);
        msp += __shfl_xor_sync(0xffffffffu, msp, m);
    }
    if ((tid & 31) == 0) { rA[tid >> 5] = ds; rB[tid >> 5] = os; rC[tid >> 5] = msp; }
    __syncthreads();
    if (tid == 0) {
        float dsum = 0.f, osum = 0.f, msum = 0.f;
#pragma unroll
        for (int i = 0; i < 8; ++i) { dsum += rA[i]; osum += rB[i]; msum += rC[i]; }
        float bd = (float)BN * (float)DD;
        float contrib = w * dsum / bd + 2.f * w * osum / (bd * (float)(DD - 1));
        atomicAdd(&g_cs_acc, contrib);
        if (r == 0) atomicAdd(&g_ms_acc, msum);
    }
    __threadfence();
    __syncthreads();
    if (tid == 0) {
        int v = atomicAdd(&g_tickF, 1);
        isLast = (v == gridDim.x - 1) ? 1 : 0;
    }
    __syncthreads();
    if (!isLast) return;
    if (tid == 0) {
        out_scalars[0] = g_ms_acc / ((float)BN * (float)DD);
        out_scalars[1] = g_cs_acc;
        g_tickF = 0;
    }
}

extern "C" void kernel_launch(void* const* d_in, const int* in_sizes, int n_in,
                              void* d_out, int out_size) {
    const float* x = (const float*)d_in[0];
    const float* c = (const float*)d_in[1];
    float* out = (float*)d_out;

    k_passA<<<NBLK_A, 128>>>(x, c, out);
    k_passB<<<1, 256>>>();
    k_passC<<<NCH, 128>>>();
    k_passE<<<NBLK_E, 256>>>(x);   // launch index 3 -> profiled next round
    k_passF1<<<KC * 8, 256>>>(c, out + (out_size - 2));
}